// round 1
// baseline (speedup 1.0000x reference)
#include <cuda_runtime.h>
#include <math.h>

#define BATCH 4
#define NSP   4096      // H*W spatial tokens
#define DM    512
#define NH    8
#define DH    64
#define NG    256       // groups (16x16)
#define JL    8         // latents per group
#define NLAT  2048      // NG*JL
#define EPSV  1e-5f

// ---------------- scratch (device globals; no allocs allowed) ----------------
__device__ float g_mod[BATCH * 1024];          // shift|scale per batch
__device__ float g_lat[BATCH * JL * DM];       // modulated latents (residual)
__device__ float g_qh [BATCH * JL * DM];       // q heads post head-LN
__device__ float g_kvn[BATCH * NSP * DM];      // LN(spatial)
__device__ float g_k  [BATCH * NSP * DM];      // k proj (head-LN applied in place)
__device__ float g_v  [BATCH * NSP * DM];      // v proj
__device__ float g_ao [BATCH * NLAT * DM];     // attention output

// ---------------- 1) mod = cond @ Wad^T + bad  (B x 1024) ----------------
__global__ void mod_kernel(const float* __restrict__ cond,
                           const float* __restrict__ Wad,
                           const float* __restrict__ bad) {
    __shared__ float cs[512];
    int b = blockIdx.y, t = threadIdx.x;
    cs[t]       = cond[b * 512 + t];
    cs[t + 256] = cond[b * 512 + t + 256];
    __syncthreads();
    int o = blockIdx.x * 256 + t;
    float acc = bad[o];
    const float4* w  = (const float4*)(Wad + (size_t)o * 512);
    const float4* c4 = (const float4*)cs;
    #pragma unroll 8
    for (int k = 0; k < 128; k++) {
        float4 wv = w[k], cv = c4[k];
        acc += wv.x * cv.x + wv.y * cv.y + wv.z * cv.z + wv.w * cv.w;
    }
    g_mod[b * 1024 + o] = acc;
}

// ------ 2) latents: modulate -> LN -> @Wq^T+bq -> head-LN  (32 rows) ------
__global__ void latq_kernel(const float* __restrict__ lt, const float* __restrict__ lp,
                            const float* __restrict__ Wq, const float* __restrict__ bq,
                            const float* __restrict__ nqg, const float* __restrict__ nqb,
                            const float* __restrict__ qng, const float* __restrict__ qnb) {
    __shared__ float r1[512], r2[512], sval[512];
    int b = blockIdx.x >> 3, j = blockIdx.x & 7;
    int t = threadIdx.x;

    float base  = lt[j * DM + t] + lp[j * DM + t];
    float shift = g_mod[b * 1024 + t];
    float scale = g_mod[b * 1024 + 512 + t];
    float lat   = base * (1.f + scale) + shift;
    g_lat[(size_t)blockIdx.x * DM + t] = lat;

    r1[t] = lat; r2[t] = lat * lat;
    __syncthreads();
    for (int s = 256; s >= 1; s >>= 1) {
        if (t < s) { r1[t] += r1[t + s]; r2[t] += r2[t + s]; }
        __syncthreads();
    }
    float mu  = r1[0] * (1.f / 512.f);
    float var = r2[0] * (1.f / 512.f) - mu * mu;
    float rs  = rsqrtf(var + EPSV);
    sval[t] = (lat - mu) * rs * nqg[t] + nqb[t];
    __syncthreads();

    float acc = bq[t];
    const float4* w  = (const float4*)(Wq + (size_t)t * DM);
    const float4* s4 = (const float4*)sval;
    #pragma unroll 8
    for (int k = 0; k < 128; k++) {
        float4 wv = w[k], sv = s4[k];
        acc += wv.x * sv.x + wv.y * sv.y + wv.z * sv.z + wv.w * sv.w;
    }
    __syncthreads();

    // head LN over 64
    r1[t] = acc; r2[t] = acc * acc;
    __syncthreads();
    for (int s = 32; s >= 1; s >>= 1) {
        if ((t & 63) < s) { r1[t] += r1[t + s]; r2[t] += r2[t + s]; }
        __syncthreads();
    }
    int hb = t & ~63, l = t & 63;
    float mu2  = r1[hb] * (1.f / 64.f);
    float var2 = r2[hb] * (1.f / 64.f) - mu2 * mu2;
    g_qh[(size_t)blockIdx.x * DM + t] =
        (acc - mu2) * rsqrtf(var2 + EPSV) * qng[l] + qnb[l];
}

// ---------------- 3) kv = LN(spatial)  (16384 rows) ----------------
__global__ void lnkv_kernel(const float* __restrict__ sp,
                            const float* __restrict__ gg,
                            const float* __restrict__ bb) {
    int row = blockIdx.x, t = threadIdx.x;
    float4 x = ((const float4*)(sp + (size_t)row * DM))[t];
    float s  = x.x + x.y + x.z + x.w;
    float s2 = x.x * x.x + x.y * x.y + x.z * x.z + x.w * x.w;
    #pragma unroll
    for (int o = 16; o >= 1; o >>= 1) {
        s  += __shfl_xor_sync(0xffffffffu, s,  o);
        s2 += __shfl_xor_sync(0xffffffffu, s2, o);
    }
    __shared__ float a1[4], a2[4];
    int w = t >> 5, lane = t & 31;
    if (!lane) { a1[w] = s; a2[w] = s2; }
    __syncthreads();
    s  = a1[0] + a1[1] + a1[2] + a1[3];
    s2 = a2[0] + a2[1] + a2[2] + a2[3];
    float mu  = s * (1.f / 512.f);
    float var = s2 * (1.f / 512.f) - mu * mu;
    float r   = rsqrtf(var + EPSV);
    float4 gv = ((const float4*)gg)[t], bv = ((const float4*)bb)[t];
    float4 o4;
    o4.x = (x.x - mu) * r * gv.x + bv.x;
    o4.y = (x.y - mu) * r * gv.y + bv.y;
    o4.z = (x.z - mu) * r * gv.z + bv.z;
    o4.w = (x.w - mu) * r * gv.w + bv.w;
    ((float4*)(g_kvn + (size_t)row * DM))[t] = o4;
}

// ---------------- 4) tiled fp32 GEMM: C = A(Mx512) @ W(Ncolsx512)^T + bias ----------------
// MODE 1: also add latent residual (final output)
template <int MODE>
__global__ void __launch_bounds__(256) gemm_nt(const float* __restrict__ A,
                                               const float* __restrict__ W,
                                               const float* __restrict__ bias,
                                               float* __restrict__ C,
                                               int Ncols,
                                               const float* __restrict__ resid) {
    __shared__ float As[16][132];
    __shared__ float Ws[16][132];
    int tid = threadIdx.x;
    int tx = tid & 15, ty = tid >> 4;
    const float* Ab = A + (size_t)(blockIdx.y * 128) * 512;
    const float* Wb = W + (size_t)(blockIdx.x * 128) * 512;
    float acc[8][8];
    #pragma unroll
    for (int i = 0; i < 8; i++)
        #pragma unroll
        for (int j = 0; j < 8; j++) acc[i][j] = 0.f;

    for (int kb = 0; kb < 512; kb += 16) {
        #pragma unroll
        for (int l = 0; l < 2; l++) {
            int p = tid + l * 256;
            int m = p >> 2, kv = p & 3;
            float4 av = *(const float4*)(Ab + (size_t)m * 512 + kb + kv * 4);
            As[kv * 4 + 0][m] = av.x; As[kv * 4 + 1][m] = av.y;
            As[kv * 4 + 2][m] = av.z; As[kv * 4 + 3][m] = av.w;
            float4 wv = *(const float4*)(Wb + (size_t)m * 512 + kb + kv * 4);
            Ws[kv * 4 + 0][m] = wv.x; Ws[kv * 4 + 1][m] = wv.y;
            Ws[kv * 4 + 2][m] = wv.z; Ws[kv * 4 + 3][m] = wv.w;
        }
        __syncthreads();
        #pragma unroll
        for (int kk = 0; kk < 16; kk++) {
            float a[8], w8[8];
            #pragma unroll
            for (int i = 0; i < 8; i++) a[i] = As[kk][i * 16 + ty];
            #pragma unroll
            for (int j = 0; j < 8; j++) w8[j] = Ws[kk][j * 16 + tx];
            #pragma unroll
            for (int i = 0; i < 8; i++)
                #pragma unroll
                for (int j = 0; j < 8; j++) acc[i][j] += a[i] * w8[j];
        }
        __syncthreads();
    }

    int col0 = blockIdx.x * 128, row0 = blockIdx.y * 128;
    #pragma unroll
    for (int i = 0; i < 8; i++) {
        int row = row0 + i * 16 + ty;
        const float* rres = nullptr;
        if (MODE == 1) rres = resid + (size_t)(((row >> 11) << 3) + (row & 7)) * 512;
        #pragma unroll
        for (int j = 0; j < 8; j++) {
            int col = col0 + j * 16 + tx;
            float v = acc[i][j] + bias[col];
            if (MODE == 1) v += rres[col];
            C[(size_t)row * Ncols + col] = v;
        }
    }
}

// ---------------- 5) per-head LN on K projection (in place) ----------------
__global__ void headln_kernel(const float* __restrict__ gg, const float* __restrict__ bb) {
    __shared__ float r1[512], r2[512];
    int row = blockIdx.x, t = threadIdx.x;
    float x = g_k[(size_t)row * DM + t];
    r1[t] = x; r2[t] = x * x;
    __syncthreads();
    for (int s = 32; s >= 1; s >>= 1) {
        if ((t & 63) < s) { r1[t] += r1[t + s]; r2[t] += r2[t + s]; }
        __syncthreads();
    }
    int hb = t & ~63, l = t & 63;
    float mu  = r1[hb] * (1.f / 64.f);
    float var = r2[hb] * (1.f / 64.f) - mu * mu;
    g_k[(size_t)row * DM + t] = (x - mu) * rsqrtf(var + EPSV) * gg[l] + bb[l];
}

// ---------------- 6) grouped attention: per (b,g), 8 heads x 8 q x 16 k ----------------
#define KS_STRIDE 514
#define SMEM_ATTN ((4096 + 16 * KS_STRIDE + 1024) * 4)

__global__ void __launch_bounds__(256) attn_kernel() {
    extern __shared__ float sm[];
    float* qs = sm;                        // 8 x 512
    float* ks = sm + 4096;                 // 16 x KS_STRIDE
    float* ps = sm + 4096 + 16 * KS_STRIDE;// 8 heads x 8 q x 16 k
    __shared__ int tok[16];

    int g = blockIdx.x, b = blockIdx.y;
    int tid = threadIdx.x;
    if (tid < 16) {
        int gr = g >> 4, gc = g & 15;
        tok[tid] = ((gr << 2) + (tid >> 2)) * 64 + (gc << 2) + (tid & 3);
    }
    __syncthreads();

    {
        const float4* src = (const float4*)(g_qh + (size_t)b * JL * DM);
        float4* dst = (float4*)qs;
        #pragma unroll
        for (int p = tid; p < 1024; p += 256) dst[p] = src[p];
    }
    for (int p = tid; p < 16 * 512; p += 256) {
        int r = p >> 9, c = p & 511;
        ks[r * KS_STRIDE + c] = g_k[((size_t)(b * NSP + tok[r])) * DM + c];
    }
    __syncthreads();

    int h = tid >> 5, lane = tid & 31;

    // scores: lane handles 4 (q,k) pairs
    float pr[4];
    #pragma unroll
    for (int i = 0; i < 4; i++) {
        int p = lane + 32 * i;
        int q = p >> 4, k = p & 15;
        const float* qrow = qs + q * DM + h * DH;
        const float* krow = ks + k * KS_STRIDE + h * DH;
        float s = 0.f;
        #pragma unroll
        for (int d = 0; d < DH; d++) s += qrow[d] * krow[d];
        pr[i] = s * 0.125f;
    }
    // softmax over 16 lanes (same q shares a 16-lane group)
    #pragma unroll
    for (int i = 0; i < 4; i++) {
        float m = pr[i];
        #pragma unroll
        for (int o = 1; o < 16; o <<= 1) m = fmaxf(m, __shfl_xor_sync(0xffffffffu, m, o));
        float e = __expf(pr[i] - m);
        float ssum = e;
        #pragma unroll
        for (int o = 1; o < 16; o <<= 1) ssum += __shfl_xor_sync(0xffffffffu, ssum, o);
        pr[i] = e / ssum;
    }
    #pragma unroll
    for (int i = 0; i < 4; i++) ps[h * 128 + lane + 32 * i] = pr[i];
    __syncwarp();

    // P @ V, V in registers (lane owns cols lane and lane+32 of its head)
    float v0[16], v1[16];
    #pragma unroll
    for (int k = 0; k < 16; k++) {
        const float* vrow = g_v + ((size_t)(b * NSP + tok[k])) * DM + h * DH;
        v0[k] = vrow[lane]; v1[k] = vrow[lane + 32];
    }
    #pragma unroll
    for (int q = 0; q < 8; q++) {
        float o0 = 0.f, o1 = 0.f;
        #pragma unroll
        for (int k = 0; k < 16; k++) {
            float pqk = ps[h * 128 + q * 16 + k];
            o0 += pqk * v0[k]; o1 += pqk * v1[k];
        }
        size_t base = ((size_t)(b * NLAT + g * JL + q)) * DM + h * DH;
        g_ao[base + lane]      = o0;
        g_ao[base + lane + 32] = o1;
    }
}

// ---------------- launch ----------------
extern "C" void kernel_launch(void* const* d_in, const int* in_sizes, int n_in,
                              void* d_out, int out_size) {
    const float* spatial = (const float*)d_in[0];
    const float* cond    = (const float*)d_in[1];
    const float* lt      = (const float*)d_in[2];
    const float* lp      = (const float*)d_in[3];
    const float* Wq      = (const float*)d_in[4];
    const float* bq      = (const float*)d_in[5];
    const float* Wk      = (const float*)d_in[6];
    const float* bk      = (const float*)d_in[7];
    const float* Wv      = (const float*)d_in[8];
    const float* bv      = (const float*)d_in[9];
    const float* Wo      = (const float*)d_in[10];
    const float* bo      = (const float*)d_in[11];
    const float* Wad     = (const float*)d_in[12];
    const float* bad     = (const float*)d_in[13];
    const float* qn_g    = (const float*)d_in[14];
    const float* qn_b    = (const float*)d_in[15];
    const float* kn_g    = (const float*)d_in[16];
    const float* kn_b    = (const float*)d_in[17];
    const float* nq_g    = (const float*)d_in[18];
    const float* nq_b    = (const float*)d_in[19];
    const float* nkv_g   = (const float*)d_in[20];
    const float* nkv_b   = (const float*)d_in[21];
    float* out = (float*)d_out;

    float *p_kvn, *p_k, *p_v, *p_ao, *p_lat;
    cudaGetSymbolAddress((void**)&p_kvn, g_kvn);
    cudaGetSymbolAddress((void**)&p_k,   g_k);
    cudaGetSymbolAddress((void**)&p_v,   g_v);
    cudaGetSymbolAddress((void**)&p_ao,  g_ao);
    cudaGetSymbolAddress((void**)&p_lat, g_lat);

    mod_kernel <<<dim3(4, BATCH), 256>>>(cond, Wad, bad);
    latq_kernel<<<BATCH * JL, 512>>>(lt, lp, Wq, bq, nq_g, nq_b, qn_g, qn_b);
    lnkv_kernel<<<BATCH * NSP, 128>>>(spatial, nkv_g, nkv_b);
    gemm_nt<0> <<<dim3(4, 128), 256>>>(p_kvn, Wk, bk, p_k, 512, nullptr);
    gemm_nt<0> <<<dim3(4, 128), 256>>>(p_kvn, Wv, bv, p_v, 512, nullptr);
    headln_kernel<<<BATCH * NSP, 512>>>(kn_g, kn_b);
    cudaFuncSetAttribute(attn_kernel, cudaFuncAttributeMaxDynamicSharedMemorySize, SMEM_ATTN);
    attn_kernel<<<dim3(NG, BATCH), 256, SMEM_ATTN>>>();
    gemm_nt<1> <<<dim3(4, 64), 256>>>(p_ao, Wo, bo, out, 512, p_lat);
}

// round 3
// speedup vs baseline: 2.9573x; 2.9573x over previous
#include <cuda_runtime.h>
#include <math.h>
#include <stdint.h>

#define BATCH 4
#define NSP   4096      // H*W spatial tokens
#define DM    512
#define NH    8
#define DH    64
#define NG    256       // groups (16x16)
#define JL    8         // latents per group
#define NLAT  2048      // NG*JL
#define EPSV  1e-5f

// ---------------- helpers ----------------
__device__ __forceinline__ float tf32r(float x) {
    uint32_t u;
    asm("cvt.rna.tf32.f32 %0, %1;" : "=r"(u) : "f"(x));
    return __uint_as_float(u);
}

#define MMA_TF32(d, a, b) \
    asm volatile("mma.sync.aligned.m16n8k8.row.col.f32.tf32.tf32.f32 " \
        "{%0,%1,%2,%3}, {%4,%5,%6,%7}, {%8,%9}, {%0,%1,%2,%3};" \
        : "+f"((d)[0]), "+f"((d)[1]), "+f"((d)[2]), "+f"((d)[3]) \
        : "r"((a)[0]), "r"((a)[1]), "r"((a)[2]), "r"((a)[3]), \
          "r"((b)[0]), "r"((b)[1]))

__device__ __forceinline__ void cp_async16(uint32_t smem_addr, const void* gptr) {
    asm volatile("cp.async.cg.shared.global [%0], [%1], 16;"
        :: "r"(smem_addr), "l"(gptr));
}
#define CP_COMMIT()  asm volatile("cp.async.commit_group;" ::: "memory")
#define CP_WAIT(N)   asm volatile("cp.async.wait_group %0;" :: "n"(N) : "memory")

__device__ __forceinline__ uint32_t smem_u32(const void* p) {
    uint32_t a;
    asm("{ .reg .u64 t; cvta.to.shared.u64 t, %1; cvt.u32.u64 %0, t; }" : "=r"(a) : "l"(p));
    return a;
}

// ---------------- scratch (device globals; no allocs allowed) ----------------
__device__ float g_mod[BATCH * 1024];
__device__ float g_lat[BATCH * JL * DM];        // modulated latents (residual, fp32)
__device__ float g_qh [BATCH * JL * DM];        // q heads post head-LN (fp32)
__device__ float g_kvn[BATCH * NSP * DM];       // LN(spatial), tf32-rounded
__device__ float g_k  [BATCH * NSP * DM];       // k proj, head-LN fused (fp32)
__device__ float g_v  [BATCH * NSP * DM];       // v proj (fp32)
__device__ float g_ao [BATCH * NLAT * DM];      // attention out, tf32-rounded
__device__ float g_wk [DM * DM];                // tf32-rounded weights
__device__ float g_wv [DM * DM];
__device__ float g_wo [DM * DM];

// ---------------- 0) weight tf32 rounding (one-shot cheap pass) ----------------
__global__ void wcvt_kernel(const float* __restrict__ src, float* __restrict__ dst) {
    int i = blockIdx.x * 256 + threadIdx.x;
    float4 v = ((const float4*)src)[i];
    v.x = tf32r(v.x); v.y = tf32r(v.y); v.z = tf32r(v.z); v.w = tf32r(v.w);
    ((float4*)dst)[i] = v;
}

// ---------------- 1) mod = cond @ Wad^T + bad  (B x 1024) ----------------
__global__ void mod_kernel(const float* __restrict__ cond,
                           const float* __restrict__ Wad,
                           const float* __restrict__ bad) {
    __shared__ float cs[512];
    int b = blockIdx.y, t = threadIdx.x;
    cs[t]       = cond[b * 512 + t];
    cs[t + 256] = cond[b * 512 + t + 256];
    __syncthreads();
    int o = blockIdx.x * 256 + t;
    float acc = bad[o];
    const float4* w  = (const float4*)(Wad + (size_t)o * 512);
    const float4* c4 = (const float4*)cs;
    #pragma unroll 8
    for (int k = 0; k < 128; k++) {
        float4 wv = w[k], cv = c4[k];
        acc += wv.x * cv.x + wv.y * cv.y + wv.z * cv.z + wv.w * cv.w;
    }
    g_mod[b * 1024 + o] = acc;
}

// ------ 2) latents: modulate -> LN -> @Wq^T+bq -> head-LN  (32 rows) ------
__global__ void latq_kernel(const float* __restrict__ lt, const float* __restrict__ lp,
                            const float* __restrict__ Wq, const float* __restrict__ bq,
                            const float* __restrict__ nqg, const float* __restrict__ nqb,
                            const float* __restrict__ qng, const float* __restrict__ qnb) {
    __shared__ float r1[512], r2[512], sval[512];
    int b = blockIdx.x >> 3, j = blockIdx.x & 7;
    int t = threadIdx.x;

    float base  = lt[j * DM + t] + lp[j * DM + t];
    float shift = g_mod[b * 1024 + t];
    float scale = g_mod[b * 1024 + 512 + t];
    float lat   = base * (1.f + scale) + shift;
    g_lat[(size_t)blockIdx.x * DM + t] = lat;

    r1[t] = lat; r2[t] = lat * lat;
    __syncthreads();
    for (int s = 256; s >= 1; s >>= 1) {
        if (t < s) { r1[t] += r1[t + s]; r2[t] += r2[t + s]; }
        __syncthreads();
    }
    float mu  = r1[0] * (1.f / 512.f);
    float var = r2[0] * (1.f / 512.f) - mu * mu;
    float rs  = rsqrtf(var + EPSV);
    sval[t] = (lat - mu) * rs * nqg[t] + nqb[t];
    __syncthreads();

    float acc = bq[t];
    const float4* w  = (const float4*)(Wq + (size_t)t * DM);
    const float4* s4 = (const float4*)sval;
    #pragma unroll 8
    for (int k = 0; k < 128; k++) {
        float4 wv = w[k], sv = s4[k];
        acc += wv.x * sv.x + wv.y * sv.y + wv.z * sv.z + wv.w * sv.w;
    }
    __syncthreads();

    r1[t] = acc; r2[t] = acc * acc;
    __syncthreads();
    for (int s = 32; s >= 1; s >>= 1) {
        if ((t & 63) < s) { r1[t] += r1[t + s]; r2[t] += r2[t + s]; }
        __syncthreads();
    }
    int hb = t & ~63, l = t & 63;
    float mu2  = r1[hb] * (1.f / 64.f);
    float var2 = r2[hb] * (1.f / 64.f) - mu2 * mu2;
    g_qh[(size_t)blockIdx.x * DM + t] =
        (acc - mu2) * rsqrtf(var2 + EPSV) * qng[l] + qnb[l];
}

// ---------------- 3) kv = LN(spatial), tf32-rounded  (16384 rows) ----------------
__global__ void lnkv_kernel(const float* __restrict__ sp,
                            const float* __restrict__ gg,
                            const float* __restrict__ bb) {
    int row = blockIdx.x, t = threadIdx.x;
    float4 x = ((const float4*)(sp + (size_t)row * DM))[t];
    float s  = x.x + x.y + x.z + x.w;
    float s2 = x.x * x.x + x.y * x.y + x.z * x.z + x.w * x.w;
    #pragma unroll
    for (int o = 16; o >= 1; o >>= 1) {
        s  += __shfl_xor_sync(0xffffffffu, s,  o);
        s2 += __shfl_xor_sync(0xffffffffu, s2, o);
    }
    __shared__ float a1[4], a2[4];
    int w = t >> 5, lane = t & 31;
    if (!lane) { a1[w] = s; a2[w] = s2; }
    __syncthreads();
    s  = a1[0] + a1[1] + a1[2] + a1[3];
    s2 = a2[0] + a2[1] + a2[2] + a2[3];
    float mu  = s * (1.f / 512.f);
    float var = s2 * (1.f / 512.f) - mu * mu;
    float r   = rsqrtf(var + EPSV);
    float4 gv = ((const float4*)gg)[t], bv = ((const float4*)bb)[t];
    float4 o4;
    o4.x = tf32r((x.x - mu) * r * gv.x + bv.x);
    o4.y = tf32r((x.y - mu) * r * gv.y + bv.y);
    o4.z = tf32r((x.z - mu) * r * gv.z + bv.z);
    o4.w = tf32r((x.w - mu) * r * gv.w + bv.w);
    ((float4*)(g_kvn + (size_t)row * DM))[t] = o4;
}

// ============ 4) tf32 mma.sync GEMM: C = A(Mx512) @ W(tile128x512)^T + bias ============
// MODE 0: fused K/V projection (bx 0-3 -> K cols + head-LN, 4-7 -> V cols)
// MODE 1: O projection + latent residual
#define AS_STRIDE 36
#define BUF_WORDS (128 * AS_STRIDE)            // one matrix buffer, words
#define SMEM_GEMM_BYTES (4 * BUF_WORDS * 4)    // A+W double buffered = 73728
#define CS_STRIDE 132

template <int MODE>
__global__ void __launch_bounds__(256, 2) mma_gemm(
    const float* __restrict__ A,
    const float* __restrict__ W0, const float* __restrict__ W1,
    const float* __restrict__ bias0, const float* __restrict__ bias1,
    float* __restrict__ C0, float* __restrict__ C1,
    const float* __restrict__ lng, const float* __restrict__ lnb,
    const float* __restrict__ resid) {
    extern __shared__ float dsm[];

    int tid = threadIdx.x;
    int bx = blockIdx.x, by = blockIdx.y;
    bool isK = (MODE == 0) ? (bx < 4) : true;
    int nb = (MODE == 0) ? (bx & 3) : bx;
    const float* W    = (MODE == 0 && !isK) ? W1 : W0;
    const float* bias = (MODE == 0 && !isK) ? bias1 : bias0;
    float* C          = (MODE == 0 && !isK) ? C1 : C0;
    int row0 = by * 128, col0 = nb * 128;
    const float* Ab = A + (size_t)row0 * 512;
    const float* Wb = W + (size_t)col0 * 512;

    int warp = tid >> 5, lane = tid & 31;
    int ln4 = lane >> 2, lnm = lane & 3;
    int wm = (warp & 1) * 64, wn = (warp >> 1) * 32;

    uint32_t sbase = smem_u32(dsm);
    int fr = tid >> 3, fc = tid & 7;   // fill: row fr(+stride), float4 col fc

    float acc[4][4][4];
    #pragma unroll
    for (int i = 0; i < 4; i++)
        #pragma unroll
        for (int j = 0; j < 4; j++)
            #pragma unroll
            for (int e = 0; e < 4; e++) acc[i][j][e] = 0.f;

    // fill chunk `c` into buffer c&1 via cp.async
    auto fill = [&](int c) {
        int buf = c & 1;
        uint32_t aB = sbase + (uint32_t)(2 * buf) * BUF_WORDS * 4;
        uint32_t wB = aB + BUF_WORDS * 4;
        int kb = c * 32;
        #pragma unroll
        for (int l = 0; l < 4; l++) {
            int r = fr + l * 32;
            uint32_t doff = (uint32_t)(r * AS_STRIDE + fc * 4) * 4;
            cp_async16(aB + doff, Ab + (size_t)r * 512 + kb + fc * 4);
            cp_async16(wB + doff, Wb + (size_t)r * 512 + kb + fc * 4);
        }
    };

    fill(0); CP_COMMIT();

    for (int c = 0; c < 16; c++) {
        if (c + 1 < 16) { fill(c + 1); CP_COMMIT(); CP_WAIT(1); }
        else            { CP_WAIT(0); }
        __syncthreads();

        const float* Abuf = dsm + (size_t)(2 * (c & 1)) * BUF_WORDS;
        const float* Wbuf = Abuf + BUF_WORDS;

        #pragma unroll
        for (int s = 0; s < 4; s++) {
            uint32_t a[4][4], bfr[4][2];
            #pragma unroll
            for (int i = 0; i < 4; i++) {
                const float* p = Abuf + (wm + i * 16 + ln4) * AS_STRIDE + s * 8 + lnm;
                a[i][0] = __float_as_uint(p[0]);
                a[i][1] = __float_as_uint(p[8 * AS_STRIDE]);
                a[i][2] = __float_as_uint(p[4]);
                a[i][3] = __float_as_uint(p[8 * AS_STRIDE + 4]);
            }
            #pragma unroll
            for (int j = 0; j < 4; j++) {
                const float* p = Wbuf + (wn + j * 8 + ln4) * AS_STRIDE + s * 8 + lnm;
                bfr[j][0] = __float_as_uint(p[0]);
                bfr[j][1] = __float_as_uint(p[4]);
            }
            #pragma unroll
            for (int i = 0; i < 4; i++)
                #pragma unroll
                for (int j = 0; j < 4; j++)
                    MMA_TF32(acc[i][j], a[i], bfr[j]);
        }
        __syncthreads();
    }

    // ---- epilogue: stage fragments to SMEM, then coalesced row-wise pass ----
    float* Cs = dsm;   // 128 x CS_STRIDE
    #pragma unroll
    for (int i = 0; i < 4; i++) {
        int r = wm + i * 16 + ln4;
        #pragma unroll
        for (int j = 0; j < 4; j++) {
            int col = wn + j * 8 + 2 * lnm;
            Cs[r * CS_STRIDE + col]           = acc[i][j][0];
            Cs[r * CS_STRIDE + col + 1]       = acc[i][j][1];
            Cs[(r + 8) * CS_STRIDE + col]     = acc[i][j][2];
            Cs[(r + 8) * CS_STRIDE + col + 1] = acc[i][j][3];
        }
    }
    __syncthreads();

    float4 bv = ((const float4*)(bias + col0))[lane];
    float4 gv, betav;
    if (MODE == 0 && isK) {
        gv    = ((const float4*)lng)[lane & 15];
        betav = ((const float4*)lnb)[lane & 15];
    }
    for (int rr = 0; rr < 16; rr++) {
        int r = warp * 16 + rr;
        float4 v = *(const float4*)(Cs + r * CS_STRIDE + lane * 4);
        v.x += bv.x; v.y += bv.y; v.z += bv.z; v.w += bv.w;
        if (MODE == 0 && isK) {
            // head-LN over 64 cols = 16-lane group
            float s  = v.x + v.y + v.z + v.w;
            float s2 = v.x * v.x + v.y * v.y + v.z * v.z + v.w * v.w;
            #pragma unroll
            for (int o = 1; o < 16; o <<= 1) {
                s  += __shfl_xor_sync(0xffffffffu, s,  o);
                s2 += __shfl_xor_sync(0xffffffffu, s2, o);
            }
            float mu  = s * (1.f / 64.f);
            float var = s2 * (1.f / 64.f) - mu * mu;
            float rq  = rsqrtf(var + EPSV);
            v.x = (v.x - mu) * rq * gv.x + betav.x;
            v.y = (v.y - mu) * rq * gv.y + betav.y;
            v.z = (v.z - mu) * rq * gv.z + betav.z;
            v.w = (v.w - mu) * rq * gv.w + betav.w;
        }
        int row = row0 + r;
        if (MODE == 1) {
            const float* rres = resid + (size_t)(((row >> 11) << 3) + (row & 7)) * 512;
            float4 rv = ((const float4*)(rres + col0))[lane];
            v.x += rv.x; v.y += rv.y; v.z += rv.z; v.w += rv.w;
        }
        ((float4*)(C + (size_t)row * 512 + col0))[lane] = v;
    }
}

// ---------------- 6) grouped attention: per (b,g), 8 heads x 8 q x 16 k ----------------
#define KS_STRIDE 514
#define SMEM_ATTN ((4096 + 16 * KS_STRIDE + 1024) * 4)

__global__ void __launch_bounds__(256) attn_kernel() {
    extern __shared__ float sm[];
    float* qs = sm;
    float* ks = sm + 4096;
    float* ps = sm + 4096 + 16 * KS_STRIDE;
    __shared__ int tok[16];

    int g = blockIdx.x, b = blockIdx.y;
    int tid = threadIdx.x;
    if (tid < 16) {
        int gr = g >> 4, gc = g & 15;
        tok[tid] = ((gr << 2) + (tid >> 2)) * 64 + (gc << 2) + (tid & 3);
    }
    __syncthreads();

    {
        const float4* src = (const float4*)(g_qh + (size_t)b * JL * DM);
        float4* dst = (float4*)qs;
        #pragma unroll
        for (int p = tid; p < 1024; p += 256) dst[p] = src[p];
    }
    for (int p = tid; p < 16 * 512; p += 256) {
        int r = p >> 9, c = p & 511;
        ks[r * KS_STRIDE + c] = g_k[((size_t)(b * NSP + tok[r])) * DM + c];
    }
    __syncthreads();

    int h = tid >> 5, lane = tid & 31;

    float pr[4];
    #pragma unroll
    for (int i = 0; i < 4; i++) {
        int p = lane + 32 * i;
        int q = p >> 4, k = p & 15;
        const float* qrow = qs + q * DM + h * DH;
        const float* krow = ks + k * KS_STRIDE + h * DH;
        float s = 0.f;
        #pragma unroll
        for (int d = 0; d < DH; d++) s += qrow[d] * krow[d];
        pr[i] = s * 0.125f;
    }
    #pragma unroll
    for (int i = 0; i < 4; i++) {
        float m = pr[i];
        #pragma unroll
        for (int o = 1; o < 16; o <<= 1) m = fmaxf(m, __shfl_xor_sync(0xffffffffu, m, o));
        float e = __expf(pr[i] - m);
        float ssum = e;
        #pragma unroll
        for (int o = 1; o < 16; o <<= 1) ssum += __shfl_xor_sync(0xffffffffu, ssum, o);
        pr[i] = e / ssum;
    }
    #pragma unroll
    for (int i = 0; i < 4; i++) ps[h * 128 + lane + 32 * i] = pr[i];
    __syncwarp();

    float v0[16], v1[16];
    #pragma unroll
    for (int k = 0; k < 16; k++) {
        const float* vrow = g_v + ((size_t)(b * NSP + tok[k])) * DM + h * DH;
        v0[k] = vrow[lane]; v1[k] = vrow[lane + 32];
    }
    #pragma unroll
    for (int q = 0; q < 8; q++) {
        float o0 = 0.f, o1 = 0.f;
        #pragma unroll
        for (int k = 0; k < 16; k++) {
            float pqk = ps[h * 128 + q * 16 + k];
            o0 += pqk * v0[k]; o1 += pqk * v1[k];
        }
        size_t base = ((size_t)(b * NLAT + g * JL + q)) * DM + h * DH;
        g_ao[base + lane]      = tf32r(o0);
        g_ao[base + lane + 32] = tf32r(o1);
    }
}

// ---------------- launch ----------------
extern "C" void kernel_launch(void* const* d_in, const int* in_sizes, int n_in,
                              void* d_out, int out_size) {
    const float* spatial = (const float*)d_in[0];
    const float* cond    = (const float*)d_in[1];
    const float* lt      = (const float*)d_in[2];
    const float* lp      = (const float*)d_in[3];
    const float* Wq      = (const float*)d_in[4];
    const float* bq      = (const float*)d_in[5];
    const float* Wk      = (const float*)d_in[6];
    const float* bk      = (const float*)d_in[7];
    const float* Wv      = (const float*)d_in[8];
    const float* bv      = (const float*)d_in[9];
    const float* Wo      = (const float*)d_in[10];
    const float* bo      = (const float*)d_in[11];
    const float* Wad     = (const float*)d_in[12];
    const float* bad     = (const float*)d_in[13];
    const float* qn_g    = (const float*)d_in[14];
    const float* qn_b    = (const float*)d_in[15];
    const float* kn_g    = (const float*)d_in[16];
    const float* kn_b    = (const float*)d_in[17];
    const float* nq_g    = (const float*)d_in[18];
    const float* nq_b    = (const float*)d_in[19];
    const float* nkv_g   = (const float*)d_in[20];
    const float* nkv_b   = (const float*)d_in[21];
    float* out = (float*)d_out;

    float *p_kvn, *p_k, *p_v, *p_ao, *p_lat, *p_wk, *p_wv, *p_wo;
    cudaGetSymbolAddress((void**)&p_kvn, g_kvn);
    cudaGetSymbolAddress((void**)&p_k,   g_k);
    cudaGetSymbolAddress((void**)&p_v,   g_v);
    cudaGetSymbolAddress((void**)&p_ao,  g_ao);
    cudaGetSymbolAddress((void**)&p_lat, g_lat);
    cudaGetSymbolAddress((void**)&p_wk,  g_wk);
    cudaGetSymbolAddress((void**)&p_wv,  g_wv);
    cudaGetSymbolAddress((void**)&p_wo,  g_wo);

    cudaFuncSetAttribute(mma_gemm<0>, cudaFuncAttributeMaxDynamicSharedMemorySize, SMEM_GEMM_BYTES);
    cudaFuncSetAttribute(mma_gemm<1>, cudaFuncAttributeMaxDynamicSharedMemorySize, SMEM_GEMM_BYTES);
    cudaFuncSetAttribute(attn_kernel, cudaFuncAttributeMaxDynamicSharedMemorySize, SMEM_ATTN);

    wcvt_kernel<<<256, 256>>>(Wk, p_wk);
    wcvt_kernel<<<256, 256>>>(Wv, p_wv);
    wcvt_kernel<<<256, 256>>>(Wo, p_wo);
    mod_kernel <<<dim3(4, BATCH), 256>>>(cond, Wad, bad);
    latq_kernel<<<BATCH * JL, 512>>>(lt, lp, Wq, bq, nq_g, nq_b, qn_g, qn_b);
    lnkv_kernel<<<BATCH * NSP, 128>>>(spatial, nkv_g, nkv_b);
    // fused K+V projection, head-LN on K in epilogue
    mma_gemm<0><<<dim3(8, 128), 256, SMEM_GEMM_BYTES>>>(
        p_kvn, p_wk, p_wv, bk, bv, p_k, p_v, kn_g, kn_b, nullptr);
    attn_kernel<<<dim3(NG, BATCH), 256, SMEM_ATTN>>>();
    // O projection + residual
    mma_gemm<1><<<dim3(4, 64), 256, SMEM_GEMM_BYTES>>>(
        p_ao, p_wo, nullptr, bo, nullptr, out, nullptr, nullptr, nullptr, p_lat);
}

// round 4
// speedup vs baseline: 3.0867x; 1.0438x over previous
#include <cuda_runtime.h>
#include <math.h>
#include <stdint.h>

#define BATCH 4
#define NSP   4096      // H*W spatial tokens
#define DM    512
#define NH    8
#define DH    64
#define NG    256       // groups (16x16)
#define JL    8         // latents per group
#define NLAT  2048      // NG*JL
#define EPSV  1e-5f

// ---------------- helpers ----------------
__device__ __forceinline__ float tf32r(float x) {
    uint32_t u;
    asm("cvt.rna.tf32.f32 %0, %1;" : "=r"(u) : "f"(x));
    return __uint_as_float(u);
}

#define MMA_TF32(d, a, b) \
    asm volatile("mma.sync.aligned.m16n8k8.row.col.f32.tf32.tf32.f32 " \
        "{%0,%1,%2,%3}, {%4,%5,%6,%7}, {%8,%9}, {%0,%1,%2,%3};" \
        : "+f"((d)[0]), "+f"((d)[1]), "+f"((d)[2]), "+f"((d)[3]) \
        : "r"((a)[0]), "r"((a)[1]), "r"((a)[2]), "r"((a)[3]), \
          "r"((b)[0]), "r"((b)[1]))

__device__ __forceinline__ void cp_async16(uint32_t smem_addr, const void* gptr) {
    asm volatile("cp.async.cg.shared.global [%0], [%1], 16;"
        :: "r"(smem_addr), "l"(gptr));
}
#define CP_COMMIT()  asm volatile("cp.async.commit_group;" ::: "memory")
#define CP_WAIT(N)   asm volatile("cp.async.wait_group %0;" :: "n"(N) : "memory")

__device__ __forceinline__ uint32_t smem_u32(const void* p) {
    uint32_t a;
    asm("{ .reg .u64 t; cvta.to.shared.u64 t, %1; cvt.u32.u64 %0, t; }" : "=r"(a) : "l"(p));
    return a;
}

// ---------------- scratch (device globals; no allocs allowed) ----------------
__device__ float g_mod[BATCH * 1024];
__device__ float g_lat[BATCH * JL * DM];        // modulated latents (residual, fp32)
__device__ float g_qh [BATCH * JL * DM];        // q heads post head-LN (fp32)
__device__ float g_kvn[BATCH * NSP * DM];       // LN(spatial), tf32-rounded
__device__ float g_k  [BATCH * NSP * DM];       // k proj, head-LN fused (fp32)
__device__ float g_v  [BATCH * NSP * DM];       // v proj (fp32)
__device__ float g_ao [BATCH * NLAT * DM];      // attention out, tf32-rounded
__device__ float g_wk [DM * DM];                // tf32-rounded weights
__device__ float g_wv [DM * DM];
__device__ float g_wo [DM * DM];

// ---------------- 0) weight tf32 rounding, all 3 weights in one launch ----------------
__global__ void wcvt_kernel(const float* __restrict__ s0, float* __restrict__ d0,
                            const float* __restrict__ s1, float* __restrict__ d1,
                            const float* __restrict__ s2, float* __restrict__ d2) {
    int which = blockIdx.x >> 8;           // 256 blocks per matrix
    int i = (blockIdx.x & 255) * 256 + threadIdx.x;
    const float* src = (which == 0) ? s0 : (which == 1) ? s1 : s2;
    float*       dst = (which == 0) ? d0 : (which == 1) ? d1 : d2;
    float4 v = ((const float4*)src)[i];
    v.x = tf32r(v.x); v.y = tf32r(v.y); v.z = tf32r(v.z); v.w = tf32r(v.w);
    ((float4*)dst)[i] = v;
}

// ---------------- 1) mod = cond @ Wad^T + bad  (4096 outputs, 8 lanes each) ----------------
__global__ void mod_kernel(const float* __restrict__ cond,
                           const float* __restrict__ Wad,
                           const float* __restrict__ bad) {
    int t = threadIdx.x;
    int o = blockIdx.x * 32 + (t >> 3);    // 0..4095
    int sub = t & 7;
    int b = o >> 10, oo = o & 1023;
    const float4* w  = (const float4*)(Wad + (size_t)oo * 512);
    const float4* cn = (const float4*)(cond + (size_t)b * 512);
    float acc = 0.f;
    #pragma unroll
    for (int k = sub * 16; k < sub * 16 + 16; k++) {
        float4 wv = w[k], cv = cn[k];
        acc += wv.x * cv.x + wv.y * cv.y + wv.z * cv.z + wv.w * cv.w;
    }
    acc += __shfl_xor_sync(0xffffffffu, acc, 1);
    acc += __shfl_xor_sync(0xffffffffu, acc, 2);
    acc += __shfl_xor_sync(0xffffffffu, acc, 4);
    if (sub == 0) g_mod[b * 1024 + oo] = acc + bad[oo];
}

// ------ 2) latents: modulate -> LN -> @Wq^T+bq -> head-LN  (32 rows) ------
__global__ void latq_kernel(const float* __restrict__ lt, const float* __restrict__ lp,
                            const float* __restrict__ Wq, const float* __restrict__ bq,
                            const float* __restrict__ nqg, const float* __restrict__ nqb,
                            const float* __restrict__ qng, const float* __restrict__ qnb) {
    __shared__ float r1[512], r2[512], sval[512];
    int b = blockIdx.x >> 3, j = blockIdx.x & 7;
    int t = threadIdx.x;

    float base  = lt[j * DM + t] + lp[j * DM + t];
    float shift = g_mod[b * 1024 + t];
    float scale = g_mod[b * 1024 + 512 + t];
    float lat   = base * (1.f + scale) + shift;
    g_lat[(size_t)blockIdx.x * DM + t] = lat;

    r1[t] = lat; r2[t] = lat * lat;
    __syncthreads();
    for (int s = 256; s >= 1; s >>= 1) {
        if (t < s) { r1[t] += r1[t + s]; r2[t] += r2[t + s]; }
        __syncthreads();
    }
    float mu  = r1[0] * (1.f / 512.f);
    float var = r2[0] * (1.f / 512.f) - mu * mu;
    float rs  = rsqrtf(var + EPSV);
    sval[t] = (lat - mu) * rs * nqg[t] + nqb[t];
    __syncthreads();

    float acc = bq[t];
    const float4* w  = (const float4*)(Wq + (size_t)t * DM);
    const float4* s4 = (const float4*)sval;
    #pragma unroll 8
    for (int k = 0; k < 128; k++) {
        float4 wv = w[k], sv = s4[k];
        acc += wv.x * sv.x + wv.y * sv.y + wv.z * sv.z + wv.w * sv.w;
    }
    __syncthreads();

    r1[t] = acc; r2[t] = acc * acc;
    __syncthreads();
    for (int s = 32; s >= 1; s >>= 1) {
        if ((t & 63) < s) { r1[t] += r1[t + s]; r2[t] += r2[t + s]; }
        __syncthreads();
    }
    int hb = t & ~63, l = t & 63;
    float mu2  = r1[hb] * (1.f / 64.f);
    float var2 = r2[hb] * (1.f / 64.f) - mu2 * mu2;
    g_qh[(size_t)blockIdx.x * DM + t] =
        (acc - mu2) * rsqrtf(var2 + EPSV) * qng[l] + qnb[l];
}

// ---------------- 3) kv = LN(spatial), tf32-rounded  (16384 rows) ----------------
__global__ void lnkv_kernel(const float* __restrict__ sp,
                            const float* __restrict__ gg,
                            const float* __restrict__ bb) {
    int row = blockIdx.x, t = threadIdx.x;
    float4 x = ((const float4*)(sp + (size_t)row * DM))[t];
    float s  = x.x + x.y + x.z + x.w;
    float s2 = x.x * x.x + x.y * x.y + x.z * x.z + x.w * x.w;
    #pragma unroll
    for (int o = 16; o >= 1; o >>= 1) {
        s  += __shfl_xor_sync(0xffffffffu, s,  o);
        s2 += __shfl_xor_sync(0xffffffffu, s2, o);
    }
    __shared__ float a1[4], a2[4];
    int w = t >> 5, lane = t & 31;
    if (!lane) { a1[w] = s; a2[w] = s2; }
    __syncthreads();
    s  = a1[0] + a1[1] + a1[2] + a1[3];
    s2 = a2[0] + a2[1] + a2[2] + a2[3];
    float mu  = s * (1.f / 512.f);
    float var = s2 * (1.f / 512.f) - mu * mu;
    float r   = rsqrtf(var + EPSV);
    float4 gv = ((const float4*)gg)[t], bv = ((const float4*)bb)[t];
    float4 o4;
    o4.x = tf32r((x.x - mu) * r * gv.x + bv.x);
    o4.y = tf32r((x.y - mu) * r * gv.y + bv.y);
    o4.z = tf32r((x.z - mu) * r * gv.z + bv.z);
    o4.w = tf32r((x.w - mu) * r * gv.w + bv.w);
    ((float4*)(g_kvn + (size_t)row * DM))[t] = o4;
}

// ============ 4) tf32 mma.sync GEMM: 256x128 CTA tile, 64x64 warp tiles ============
// MODE 0: fused K/V projection (bx 0-3 -> K cols + head-LN, 4-7 -> V cols)
// MODE 1: O projection + latent residual
#define AS_STRIDE 36
#define WORDS_A (256 * AS_STRIDE)              // 9216
#define WORDS_W (128 * AS_STRIDE)              // 4608
#define WORDS_STAGE (WORDS_A + WORDS_W)        // 13824
#define SMEM_GEMM_BYTES (2 * WORDS_STAGE * 4)  // 110592

template <int MODE>
__global__ void __launch_bounds__(256, 1) mma_gemm(
    const float* __restrict__ A,
    const float* __restrict__ W0, const float* __restrict__ W1,
    const float* __restrict__ bias0, const float* __restrict__ bias1,
    float* __restrict__ C0, float* __restrict__ C1,
    const float* __restrict__ lng, const float* __restrict__ lnb,
    const float* __restrict__ resid) {
    extern __shared__ float dsm[];

    int tid = threadIdx.x;
    int bx = blockIdx.x, by = blockIdx.y;
    bool isK = (MODE == 0) ? (bx < 4) : false;
    int nb = (MODE == 0) ? (bx & 3) : bx;
    const float* W    = (MODE == 0 && !isK) ? W1 : W0;
    const float* bias = (MODE == 0 && !isK) ? bias1 : bias0;
    float* C          = (MODE == 0 && !isK) ? C1 : C0;
    int row0 = by * 256, col0 = nb * 128;
    const float* Ab = A + (size_t)row0 * 512;
    const float* Wb = W + (size_t)col0 * 512;

    int warp = tid >> 5, lane = tid & 31;
    int ln4 = lane >> 2, lnm = lane & 3;
    int wm = (warp & 3) * 64, wn = (warp >> 2) * 64;

    uint32_t sbase = smem_u32(dsm);
    int fr = tid >> 3, fc = tid & 7;   // fill: base row (0..31), float4 col (0..7)

    float acc[4][8][4];
    #pragma unroll
    for (int i = 0; i < 4; i++)
        #pragma unroll
        for (int j = 0; j < 8; j++)
            #pragma unroll
            for (int e = 0; e < 4; e++) acc[i][j][e] = 0.f;

    auto fill = [&](int c) {
        int buf = c & 1;
        uint32_t aB = sbase + (uint32_t)buf * WORDS_STAGE * 4;
        uint32_t wB = aB + WORDS_A * 4;
        int kb = c * 32;
        #pragma unroll
        for (int l = 0; l < 8; l++) {
            int r = fr + l * 32;
            cp_async16(aB + (uint32_t)(r * AS_STRIDE + fc * 4) * 4,
                       Ab + (size_t)r * 512 + kb + fc * 4);
        }
        #pragma unroll
        for (int l = 0; l < 4; l++) {
            int r = fr + l * 32;
            cp_async16(wB + (uint32_t)(r * AS_STRIDE + fc * 4) * 4,
                       Wb + (size_t)r * 512 + kb + fc * 4);
        }
    };

    fill(0); CP_COMMIT();

    for (int c = 0; c < 16; c++) {
        if (c + 1 < 16) { fill(c + 1); CP_COMMIT(); CP_WAIT(1); }
        else            { CP_WAIT(0); }
        __syncthreads();

        const float* Abuf = dsm + (size_t)(c & 1) * WORDS_STAGE;
        const float* Wbuf = Abuf + WORDS_A;

        #pragma unroll
        for (int s = 0; s < 4; s++) {
            uint32_t a[4][4], bfr[8][2];
            #pragma unroll
            for (int i = 0; i < 4; i++) {
                const float* p = Abuf + (wm + i * 16 + ln4) * AS_STRIDE + s * 8 + lnm;
                a[i][0] = __float_as_uint(p[0]);
                a[i][1] = __float_as_uint(p[8 * AS_STRIDE]);
                a[i][2] = __float_as_uint(p[4]);
                a[i][3] = __float_as_uint(p[8 * AS_STRIDE + 4]);
            }
            #pragma unroll
            for (int j = 0; j < 8; j++) {
                const float* p = Wbuf + (wn + j * 8 + ln4) * AS_STRIDE + s * 8 + lnm;
                bfr[j][0] = __float_as_uint(p[0]);
                bfr[j][1] = __float_as_uint(p[4]);
            }
            #pragma unroll
            for (int i = 0; i < 4; i++)
                #pragma unroll
                for (int j = 0; j < 8; j++)
                    MMA_TF32(acc[i][j], a[i], bfr[j]);
        }
        __syncthreads();
    }

    // ---- register-resident epilogue: bias (+head-LN | +residual), direct stores ----
    // thread's 16 cols per row: {wn + j*8 + 2*lnm, +1}, j=0..7; head = 64-col warp tile
    float2 b2[8];
    #pragma unroll
    for (int j = 0; j < 8; j++)
        b2[j] = *(const float2*)(bias + col0 + wn + j * 8 + 2 * lnm);
    float2 g2[8], be2[8];
    if (MODE == 0 && isK) {
        #pragma unroll
        for (int j = 0; j < 8; j++) {
            g2[j]  = *(const float2*)(lng + j * 8 + 2 * lnm);
            be2[j] = *(const float2*)(lnb + j * 8 + 2 * lnm);
        }
    }

    #pragma unroll
    for (int i = 0; i < 4; i++) {
        #pragma unroll
        for (int h = 0; h < 2; h++) {
            int row = row0 + wm + i * 16 + ln4 + 8 * h;
            float vx[8], vy[8];
            #pragma unroll
            for (int j = 0; j < 8; j++) {
                vx[j] = acc[i][j][2 * h]     + b2[j].x;
                vy[j] = acc[i][j][2 * h + 1] + b2[j].y;
            }
            if (MODE == 0 && isK) {
                float s = 0.f, s2 = 0.f;
                #pragma unroll
                for (int j = 0; j < 8; j++) {
                    s  += vx[j] + vy[j];
                    s2 += vx[j] * vx[j] + vy[j] * vy[j];
                }
                s  += __shfl_xor_sync(0xffffffffu, s, 1);
                s  += __shfl_xor_sync(0xffffffffu, s, 2);
                s2 += __shfl_xor_sync(0xffffffffu, s2, 1);
                s2 += __shfl_xor_sync(0xffffffffu, s2, 2);
                float mu  = s * (1.f / 64.f);
                float var = s2 * (1.f / 64.f) - mu * mu;
                float rq  = rsqrtf(var + EPSV);
                #pragma unroll
                for (int j = 0; j < 8; j++) {
                    vx[j] = (vx[j] - mu) * rq * g2[j].x + be2[j].x;
                    vy[j] = (vy[j] - mu) * rq * g2[j].y + be2[j].y;
                }
            }
            if (MODE == 1) {
                const float* rres = resid
                    + (size_t)(((row >> 11) << 3) + (row & 7)) * 512 + col0 + wn;
                #pragma unroll
                for (int j = 0; j < 8; j++) {
                    float2 rv = *(const float2*)(rres + j * 8 + 2 * lnm);
                    vx[j] += rv.x; vy[j] += rv.y;
                }
            }
            float* cr = C + (size_t)row * 512 + col0 + wn;
            #pragma unroll
            for (int j = 0; j < 8; j++)
                *(float2*)(cr + j * 8 + 2 * lnm) = make_float2(vx[j], vy[j]);
        }
    }
}

// ---------------- 6) grouped attention: per (b,g), 8 heads x 8 q x 16 k ----------------
#define KS_STRIDE 514
#define SMEM_ATTN ((4096 + 16 * KS_STRIDE + 1024) * 4)

__global__ void __launch_bounds__(256) attn_kernel() {
    extern __shared__ float sm[];
    float* qs = sm;
    float* ks = sm + 4096;
    float* ps = sm + 4096 + 16 * KS_STRIDE;
    __shared__ int tok[16];

    int g = blockIdx.x, b = blockIdx.y;
    int tid = threadIdx.x;
    if (tid < 16) {
        int gr = g >> 4, gc = g & 15;
        tok[tid] = ((gr << 2) + (tid >> 2)) * 64 + (gc << 2) + (tid & 3);
    }
    __syncthreads();

    {
        const float4* src = (const float4*)(g_qh + (size_t)b * JL * DM);
        float4* dst = (float4*)qs;
        #pragma unroll
        for (int p = tid; p < 1024; p += 256) dst[p] = src[p];
    }
    for (int p = tid; p < 16 * 512; p += 256) {
        int r = p >> 9, c = p & 511;
        ks[r * KS_STRIDE + c] = g_k[((size_t)(b * NSP + tok[r])) * DM + c];
    }
    __syncthreads();

    int h = tid >> 5, lane = tid & 31;

    float pr[4];
    #pragma unroll
    for (int i = 0; i < 4; i++) {
        int p = lane + 32 * i;
        int q = p >> 4, k = p & 15;
        const float* qrow = qs + q * DM + h * DH;
        const float* krow = ks + k * KS_STRIDE + h * DH;
        float s = 0.f;
        #pragma unroll
        for (int d = 0; d < DH; d++) s += qrow[d] * krow[d];
        pr[i] = s * 0.125f;
    }
    #pragma unroll
    for (int i = 0; i < 4; i++) {
        float m = pr[i];
        #pragma unroll
        for (int o = 1; o < 16; o <<= 1) m = fmaxf(m, __shfl_xor_sync(0xffffffffu, m, o));
        float e = __expf(pr[i] - m);
        float ssum = e;
        #pragma unroll
        for (int o = 1; o < 16; o <<= 1) ssum += __shfl_xor_sync(0xffffffffu, ssum, o);
        pr[i] = e / ssum;
    }
    #pragma unroll
    for (int i = 0; i < 4; i++) ps[h * 128 + lane + 32 * i] = pr[i];
    __syncwarp();

    float v0[16], v1[16];
    #pragma unroll
    for (int k = 0; k < 16; k++) {
        const float* vrow = g_v + ((size_t)(b * NSP + tok[k])) * DM + h * DH;
        v0[k] = vrow[lane]; v1[k] = vrow[lane + 32];
    }
    #pragma unroll
    for (int q = 0; q < 8; q++) {
        float o0 = 0.f, o1 = 0.f;
        #pragma unroll
        for (int k = 0; k < 16; k++) {
            float pqk = ps[h * 128 + q * 16 + k];
            o0 += pqk * v0[k]; o1 += pqk * v1[k];
        }
        size_t base = ((size_t)(b * NLAT + g * JL + q)) * DM + h * DH;
        g_ao[base + lane]      = tf32r(o0);
        g_ao[base + lane + 32] = tf32r(o1);
    }
}

// ---------------- launch ----------------
extern "C" void kernel_launch(void* const* d_in, const int* in_sizes, int n_in,
                              void* d_out, int out_size) {
    const float* spatial = (const float*)d_in[0];
    const float* cond    = (const float*)d_in[1];
    const float* lt      = (const float*)d_in[2];
    const float* lp      = (const float*)d_in[3];
    const float* Wq      = (const float*)d_in[4];
    const float* bq      = (const float*)d_in[5];
    const float* Wk      = (const float*)d_in[6];
    const float* bk      = (const float*)d_in[7];
    const float* Wv      = (const float*)d_in[8];
    const float* bv      = (const float*)d_in[9];
    const float* Wo      = (const float*)d_in[10];
    const float* bo      = (const float*)d_in[11];
    const float* Wad     = (const float*)d_in[12];
    const float* bad     = (const float*)d_in[13];
    const float* qn_g    = (const float*)d_in[14];
    const float* qn_b    = (const float*)d_in[15];
    const float* kn_g    = (const float*)d_in[16];
    const float* kn_b    = (const float*)d_in[17];
    const float* nq_g    = (const float*)d_in[18];
    const float* nq_b    = (const float*)d_in[19];
    const float* nkv_g   = (const float*)d_in[20];
    const float* nkv_b   = (const float*)d_in[21];
    float* out = (float*)d_out;

    float *p_kvn, *p_k, *p_v, *p_ao, *p_lat, *p_wk, *p_wv, *p_wo;
    cudaGetSymbolAddress((void**)&p_kvn, g_kvn);
    cudaGetSymbolAddress((void**)&p_k,   g_k);
    cudaGetSymbolAddress((void**)&p_v,   g_v);
    cudaGetSymbolAddress((void**)&p_ao,  g_ao);
    cudaGetSymbolAddress((void**)&p_lat, g_lat);
    cudaGetSymbolAddress((void**)&p_wk,  g_wk);
    cudaGetSymbolAddress((void**)&p_wv,  g_wv);
    cudaGetSymbolAddress((void**)&p_wo,  g_wo);

    cudaFuncSetAttribute(mma_gemm<0>, cudaFuncAttributeMaxDynamicSharedMemorySize, SMEM_GEMM_BYTES);
    cudaFuncSetAttribute(mma_gemm<1>, cudaFuncAttributeMaxDynamicSharedMemorySize, SMEM_GEMM_BYTES);
    cudaFuncSetAttribute(attn_kernel, cudaFuncAttributeMaxDynamicSharedMemorySize, SMEM_ATTN);

    wcvt_kernel<<<768, 256>>>(Wk, p_wk, Wv, p_wv, Wo, p_wo);
    mod_kernel <<<128, 256>>>(cond, Wad, bad);
    latq_kernel<<<BATCH * JL, 512>>>(lt, lp, Wq, bq, nq_g, nq_b, qn_g, qn_b);
    lnkv_kernel<<<BATCH * NSP, 128>>>(spatial, nkv_g, nkv_b);
    // fused K+V projection (256-row tiles), head-LN on K in epilogue
    mma_gemm<0><<<dim3(8, 64), 256, SMEM_GEMM_BYTES>>>(
        p_kvn, p_wk, p_wv, bk, bv, p_k, p_v, kn_g, kn_b, nullptr);
    attn_kernel<<<dim3(NG, BATCH), 256, SMEM_ATTN>>>();
    // O projection + residual (256-row tiles)
    mma_gemm<1><<<dim3(4, 32), 256, SMEM_GEMM_BYTES>>>(
        p_ao, p_wo, nullptr, bo, nullptr, out, nullptr, nullptr, nullptr, p_lat);
}

// round 5
// speedup vs baseline: 4.2868x; 1.3888x over previous
#include <cuda_runtime.h>
#include <cuda_fp16.h>
#include <math.h>
#include <stdint.h>

#define BATCH 4
#define NSP   4096      // H*W spatial tokens
#define DM    512
#define NH    8
#define DH    64
#define NG    256       // groups (16x16)
#define JL    8         // latents per group
#define NLAT  2048      // NG*JL
#define EPSV  1e-5f

// ---------------- helpers ----------------
#define MMA_F16(d, a, b) \
    asm volatile("mma.sync.aligned.m16n8k16.row.col.f32.f16.f16.f32 " \
        "{%0,%1,%2,%3}, {%4,%5,%6,%7}, {%8,%9}, {%0,%1,%2,%3};" \
        : "+f"((d)[0]), "+f"((d)[1]), "+f"((d)[2]), "+f"((d)[3]) \
        : "r"((a)[0]), "r"((a)[1]), "r"((a)[2]), "r"((a)[3]), \
          "r"((b)[0]), "r"((b)[1]))

__device__ __forceinline__ void cp_async16(uint32_t smem_addr, const void* gptr) {
    asm volatile("cp.async.cg.shared.global [%0], [%1], 16;"
        :: "r"(smem_addr), "l"(gptr));
}
#define CP_COMMIT()  asm volatile("cp.async.commit_group;" ::: "memory")
#define CP_WAIT(N)   asm volatile("cp.async.wait_group %0;" :: "n"(N) : "memory")

__device__ __forceinline__ uint32_t smem_u32(const void* p) {
    uint32_t a;
    asm("{ .reg .u64 t; cvta.to.shared.u64 t, %1; cvt.u32.u64 %0, t; }" : "=r"(a) : "l"(p));
    return a;
}

// ---------------- scratch (device globals; no allocs allowed) ----------------
__device__ float  g_mod[BATCH * 1024];
__device__ float  g_lat[BATCH * JL * DM];       // modulated latents (residual, fp32)
__device__ float  g_qh [BATCH * JL * DM];       // q heads post head-LN (fp32)
__device__ __half g_kvn[BATCH * NSP * DM];      // LN(spatial), fp16
__device__ float  g_k  [BATCH * NSP * DM];      // k proj, head-LN fused (fp32)
__device__ float  g_v  [BATCH * NSP * DM];      // v proj (fp32)
__device__ __half g_ao [BATCH * NLAT * DM];     // attention out, fp16
__device__ __half g_wk [DM * DM];               // fp16 weights
__device__ __half g_wv [DM * DM];
__device__ __half g_wo [DM * DM];

// ---------------- 0) weight fp16 conversion, all 3 weights in one launch ----------------
__global__ void wcvt_kernel(const float* __restrict__ s0, __half* __restrict__ d0,
                            const float* __restrict__ s1, __half* __restrict__ d1,
                            const float* __restrict__ s2, __half* __restrict__ d2) {
    int which = blockIdx.x >> 8;           // 256 blocks per matrix
    int i = (blockIdx.x & 255) * 256 + threadIdx.x;   // float4 index
    const float* src = (which == 0) ? s0 : (which == 1) ? s1 : s2;
    __half*      dst = (which == 0) ? d0 : (which == 1) ? d1 : d2;
    float4 v = ((const float4*)src)[i];
    __half2 h0 = __floats2half2_rn(v.x, v.y);
    __half2 h1 = __floats2half2_rn(v.z, v.w);
    ((__half2*)dst)[2 * i]     = h0;
    ((__half2*)dst)[2 * i + 1] = h1;
}

// ---------------- 1) mod = cond @ Wad^T + bad  (4096 outputs, 8 lanes each) ----------------
__global__ void mod_kernel(const float* __restrict__ cond,
                           const float* __restrict__ Wad,
                           const float* __restrict__ bad) {
    int t = threadIdx.x;
    int o = blockIdx.x * 32 + (t >> 3);    // 0..4095
    int sub = t & 7;
    int b = o >> 10, oo = o & 1023;
    const float4* w  = (const float4*)(Wad + (size_t)oo * 512);
    const float4* cn = (const float4*)(cond + (size_t)b * 512);
    float acc = 0.f;
    #pragma unroll
    for (int k = sub * 16; k < sub * 16 + 16; k++) {
        float4 wv = w[k], cv = cn[k];
        acc += wv.x * cv.x + wv.y * cv.y + wv.z * cv.z + wv.w * cv.w;
    }
    acc += __shfl_xor_sync(0xffffffffu, acc, 1);
    acc += __shfl_xor_sync(0xffffffffu, acc, 2);
    acc += __shfl_xor_sync(0xffffffffu, acc, 4);
    if (sub == 0) g_mod[b * 1024 + oo] = acc + bad[oo];
}

// ------ 2) latents: modulate -> LN -> @Wq^T+bq -> head-LN  (32 rows) ------
__global__ void latq_kernel(const float* __restrict__ lt, const float* __restrict__ lp,
                            const float* __restrict__ Wq, const float* __restrict__ bq,
                            const float* __restrict__ nqg, const float* __restrict__ nqb,
                            const float* __restrict__ qng, const float* __restrict__ qnb) {
    __shared__ float r1[512], r2[512], sval[512];
    int b = blockIdx.x >> 3, j = blockIdx.x & 7;
    int t = threadIdx.x;

    float base  = lt[j * DM + t] + lp[j * DM + t];
    float shift = g_mod[b * 1024 + t];
    float scale = g_mod[b * 1024 + 512 + t];
    float lat   = base * (1.f + scale) + shift;
    g_lat[(size_t)blockIdx.x * DM + t] = lat;

    r1[t] = lat; r2[t] = lat * lat;
    __syncthreads();
    for (int s = 256; s >= 1; s >>= 1) {
        if (t < s) { r1[t] += r1[t + s]; r2[t] += r2[t + s]; }
        __syncthreads();
    }
    float mu  = r1[0] * (1.f / 512.f);
    float var = r2[0] * (1.f / 512.f) - mu * mu;
    float rs  = rsqrtf(var + EPSV);
    sval[t] = (lat - mu) * rs * nqg[t] + nqb[t];
    __syncthreads();

    float acc = bq[t];
    const float4* w  = (const float4*)(Wq + (size_t)t * DM);
    const float4* s4 = (const float4*)sval;
    #pragma unroll 8
    for (int k = 0; k < 128; k++) {
        float4 wv = w[k], sv = s4[k];
        acc += wv.x * sv.x + wv.y * sv.y + wv.z * sv.z + wv.w * sv.w;
    }
    __syncthreads();

    r1[t] = acc; r2[t] = acc * acc;
    __syncthreads();
    for (int s = 32; s >= 1; s >>= 1) {
        if ((t & 63) < s) { r1[t] += r1[t + s]; r2[t] += r2[t + s]; }
        __syncthreads();
    }
    int hb = t & ~63, l = t & 63;
    float mu2  = r1[hb] * (1.f / 64.f);
    float var2 = r2[hb] * (1.f / 64.f) - mu2 * mu2;
    g_qh[(size_t)blockIdx.x * DM + t] =
        (acc - mu2) * rsqrtf(var2 + EPSV) * qng[l] + qnb[l];
}

// ---------------- 3) kv = LN(spatial), fp16 out  (16384 rows) ----------------
__global__ void lnkv_kernel(const float* __restrict__ sp,
                            const float* __restrict__ gg,
                            const float* __restrict__ bb) {
    int row = blockIdx.x, t = threadIdx.x;
    float4 x = ((const float4*)(sp + (size_t)row * DM))[t];
    float s  = x.x + x.y + x.z + x.w;
    float s2 = x.x * x.x + x.y * x.y + x.z * x.z + x.w * x.w;
    #pragma unroll
    for (int o = 16; o >= 1; o >>= 1) {
        s  += __shfl_xor_sync(0xffffffffu, s,  o);
        s2 += __shfl_xor_sync(0xffffffffu, s2, o);
    }
    __shared__ float a1[4], a2[4];
    int w = t >> 5, lane = t & 31;
    if (!lane) { a1[w] = s; a2[w] = s2; }
    __syncthreads();
    s  = a1[0] + a1[1] + a1[2] + a1[3];
    s2 = a2[0] + a2[1] + a2[2] + a2[3];
    float mu  = s * (1.f / 512.f);
    float var = s2 * (1.f / 512.f) - mu * mu;
    float r   = rsqrtf(var + EPSV);
    float4 gv = ((const float4*)gg)[t], bv = ((const float4*)bb)[t];
    __half2 h0 = __floats2half2_rn((x.x - mu) * r * gv.x + bv.x,
                                   (x.y - mu) * r * gv.y + bv.y);
    __half2 h1 = __floats2half2_rn((x.z - mu) * r * gv.z + bv.z,
                                   (x.w - mu) * r * gv.w + bv.w);
    __half2* orow = (__half2*)(g_kvn + (size_t)row * DM);
    orow[2 * t]     = h0;
    orow[2 * t + 1] = h1;
}

// ============ 4) fp16 mma.sync GEMM: 256x128 CTA tile, 64x64 warp tiles ============
// MODE 0: fused K/V projection (bx 0-3 -> K cols + head-LN, 4-7 -> V cols)
// MODE 1: O projection + latent residual
#define AS_STRIDE 72                              // halfs per row (64 + 8 pad)
#define HALFS_A (256 * AS_STRIDE)                 // 18432
#define HALFS_W (128 * AS_STRIDE)                 // 9216
#define HALFS_STAGE (HALFS_A + HALFS_W)           // 27648
#define SMEM_GEMM_BYTES (2 * HALFS_STAGE * 2)     // 110592

template <int MODE>
__global__ void __launch_bounds__(256, 1) mma_gemm(
    const __half* __restrict__ A,
    const __half* __restrict__ W0, const __half* __restrict__ W1,
    const float* __restrict__ bias0, const float* __restrict__ bias1,
    float* __restrict__ C0, float* __restrict__ C1,
    const float* __restrict__ lng, const float* __restrict__ lnb,
    const float* __restrict__ resid) {
    extern __shared__ __half hsm[];

    int tid = threadIdx.x;
    int bx = blockIdx.x, by = blockIdx.y;
    bool isK = (MODE == 0) ? (bx < 4) : false;
    int nb = (MODE == 0) ? (bx & 3) : bx;
    const __half* W   = (MODE == 0 && !isK) ? W1 : W0;
    const float* bias = (MODE == 0 && !isK) ? bias1 : bias0;
    float* C          = (MODE == 0 && !isK) ? C1 : C0;
    int row0 = by * 256, col0 = nb * 128;
    const __half* Ab = A + (size_t)row0 * 512;
    const __half* Wb = W + (size_t)col0 * 512;

    int warp = tid >> 5, lane = tid & 31;
    int ln4 = lane >> 2, lnm = lane & 3;
    int wm = (warp & 3) * 64, wn = (warp >> 2) * 64;

    uint32_t sbase = smem_u32(hsm);
    int fr = tid >> 3, fc = tid & 7;   // fill: base row (0..31), 16B col (0..7)

    float acc[4][8][4];
    #pragma unroll
    for (int i = 0; i < 4; i++)
        #pragma unroll
        for (int j = 0; j < 8; j++)
            #pragma unroll
            for (int e = 0; e < 4; e++) acc[i][j][e] = 0.f;

    auto fill = [&](int c) {   // chunk c: K cols [c*64, c*64+64)
        int buf = c & 1;
        uint32_t aB = sbase + (uint32_t)buf * HALFS_STAGE * 2;
        uint32_t wB = aB + HALFS_A * 2;
        int kb = c * 64;
        #pragma unroll
        for (int l = 0; l < 8; l++) {
            int r = fr + l * 32;
            cp_async16(aB + (uint32_t)(r * AS_STRIDE + fc * 8) * 2,
                       Ab + (size_t)r * 512 + kb + fc * 8);
        }
        #pragma unroll
        for (int l = 0; l < 4; l++) {
            int r = fr + l * 32;
            cp_async16(wB + (uint32_t)(r * AS_STRIDE + fc * 8) * 2,
                       Wb + (size_t)r * 512 + kb + fc * 8);
        }
    };

    fill(0); CP_COMMIT();

    for (int c = 0; c < 8; c++) {
        if (c + 1 < 8) { fill(c + 1); CP_COMMIT(); CP_WAIT(1); }
        else           { CP_WAIT(0); }
        __syncthreads();

        const __half* Abuf = hsm + (size_t)(c & 1) * HALFS_STAGE;
        const __half* Wbuf = Abuf + HALFS_A;

        #pragma unroll
        for (int s = 0; s < 4; s++) {   // k16 steps within chunk
            uint32_t a[4][4], bfr[8][2];
            #pragma unroll
            for (int i = 0; i < 4; i++) {
                const __half* p = Abuf + (wm + i * 16 + ln4) * AS_STRIDE + s * 16 + 2 * lnm;
                a[i][0] = *(const uint32_t*)(p);
                a[i][1] = *(const uint32_t*)(p + 8 * AS_STRIDE);
                a[i][2] = *(const uint32_t*)(p + 8);
                a[i][3] = *(const uint32_t*)(p + 8 * AS_STRIDE + 8);
            }
            #pragma unroll
            for (int j = 0; j < 8; j++) {
                const __half* p = Wbuf + (wn + j * 8 + ln4) * AS_STRIDE + s * 16 + 2 * lnm;
                bfr[j][0] = *(const uint32_t*)(p);
                bfr[j][1] = *(const uint32_t*)(p + 8);
            }
            #pragma unroll
            for (int i = 0; i < 4; i++)
                #pragma unroll
                for (int j = 0; j < 8; j++)
                    MMA_F16(acc[i][j], a[i], bfr[j]);
        }
        __syncthreads();
    }

    // ---- register-resident epilogue: bias (+head-LN | +residual), direct stores ----
    float2 b2[8];
    #pragma unroll
    for (int j = 0; j < 8; j++)
        b2[j] = *(const float2*)(bias + col0 + wn + j * 8 + 2 * lnm);
    float2 g2[8], be2[8];
    if (MODE == 0 && isK) {
        #pragma unroll
        for (int j = 0; j < 8; j++) {
            g2[j]  = *(const float2*)(lng + j * 8 + 2 * lnm);
            be2[j] = *(const float2*)(lnb + j * 8 + 2 * lnm);
        }
    }

    #pragma unroll
    for (int i = 0; i < 4; i++) {
        #pragma unroll
        for (int h = 0; h < 2; h++) {
            int row = row0 + wm + i * 16 + ln4 + 8 * h;
            float vx[8], vy[8];
            #pragma unroll
            for (int j = 0; j < 8; j++) {
                vx[j] = acc[i][j][2 * h]     + b2[j].x;
                vy[j] = acc[i][j][2 * h + 1] + b2[j].y;
            }
            if (MODE == 0 && isK) {
                float s = 0.f, s2 = 0.f;
                #pragma unroll
                for (int j = 0; j < 8; j++) {
                    s  += vx[j] + vy[j];
                    s2 += vx[j] * vx[j] + vy[j] * vy[j];
                }
                s  += __shfl_xor_sync(0xffffffffu, s, 1);
                s  += __shfl_xor_sync(0xffffffffu, s, 2);
                s2 += __shfl_xor_sync(0xffffffffu, s2, 1);
                s2 += __shfl_xor_sync(0xffffffffu, s2, 2);
                float mu  = s * (1.f / 64.f);
                float var = s2 * (1.f / 64.f) - mu * mu;
                float rq  = rsqrtf(var + EPSV);
                #pragma unroll
                for (int j = 0; j < 8; j++) {
                    vx[j] = (vx[j] - mu) * rq * g2[j].x + be2[j].x;
                    vy[j] = (vy[j] - mu) * rq * g2[j].y + be2[j].y;
                }
            }
            if (MODE == 1) {
                const float* rres = resid
                    + (size_t)(((row >> 11) << 3) + (row & 7)) * 512 + col0 + wn;
                #pragma unroll
                for (int j = 0; j < 8; j++) {
                    float2 rv = *(const float2*)(rres + j * 8 + 2 * lnm);
                    vx[j] += rv.x; vy[j] += rv.y;
                }
            }
            float* cr = C + (size_t)row * 512 + col0 + wn;
            #pragma unroll
            for (int j = 0; j < 8; j++)
                *(float2*)(cr + j * 8 + 2 * lnm) = make_float2(vx[j], vy[j]);
        }
    }
}

// ---------------- 6) grouped attention: per (b,g), 8 heads x 8 q x 16 k ----------------
#define KS_STRIDE 514
#define SMEM_ATTN ((4096 + 16 * KS_STRIDE + 1024) * 4)

__global__ void __launch_bounds__(256) attn_kernel() {
    extern __shared__ float sm[];
    float* qs = sm;
    float* ks = sm + 4096;
    float* ps = sm + 4096 + 16 * KS_STRIDE;
    __shared__ int tok[16];

    int g = blockIdx.x, b = blockIdx.y;
    int tid = threadIdx.x;
    if (tid < 16) {
        int gr = g >> 4, gc = g & 15;
        tok[tid] = ((gr << 2) + (tid >> 2)) * 64 + (gc << 2) + (tid & 3);
    }
    __syncthreads();

    {
        const float4* src = (const float4*)(g_qh + (size_t)b * JL * DM);
        float4* dst = (float4*)qs;
        #pragma unroll
        for (int p = tid; p < 1024; p += 256) dst[p] = src[p];
    }
    for (int p = tid; p < 16 * 512; p += 256) {
        int r = p >> 9, c = p & 511;
        ks[r * KS_STRIDE + c] = g_k[((size_t)(b * NSP + tok[r])) * DM + c];
    }
    __syncthreads();

    int h = tid >> 5, lane = tid & 31;

    float pr[4];
    #pragma unroll
    for (int i = 0; i < 4; i++) {
        int p = lane + 32 * i;
        int q = p >> 4, k = p & 15;
        const float* qrow = qs + q * DM + h * DH;
        const float* krow = ks + k * KS_STRIDE + h * DH;
        float s = 0.f;
        #pragma unroll
        for (int d = 0; d < DH; d++) s += qrow[d] * krow[d];
        pr[i] = s * 0.125f;
    }
    #pragma unroll
    for (int i = 0; i < 4; i++) {
        float m = pr[i];
        #pragma unroll
        for (int o = 1; o < 16; o <<= 1) m = fmaxf(m, __shfl_xor_sync(0xffffffffu, m, o));
        float e = __expf(pr[i] - m);
        float ssum = e;
        #pragma unroll
        for (int o = 1; o < 16; o <<= 1) ssum += __shfl_xor_sync(0xffffffffu, ssum, o);
        pr[i] = e / ssum;
    }
    #pragma unroll
    for (int i = 0; i < 4; i++) ps[h * 128 + lane + 32 * i] = pr[i];
    __syncwarp();

    float v0[16], v1[16];
    #pragma unroll
    for (int k = 0; k < 16; k++) {
        const float* vrow = g_v + ((size_t)(b * NSP + tok[k])) * DM + h * DH;
        v0[k] = vrow[lane]; v1[k] = vrow[lane + 32];
    }
    #pragma unroll
    for (int q = 0; q < 8; q++) {
        float o0 = 0.f, o1 = 0.f;
        #pragma unroll
        for (int k = 0; k < 16; k++) {
            float pqk = ps[h * 128 + q * 16 + k];
            o0 += pqk * v0[k]; o1 += pqk * v1[k];
        }
        size_t base = ((size_t)(b * NLAT + g * JL + q)) * DM + h * DH;
        g_ao[base + lane]      = __float2half_rn(o0);
        g_ao[base + lane + 32] = __float2half_rn(o1);
    }
}

// ---------------- launch ----------------
extern "C" void kernel_launch(void* const* d_in, const int* in_sizes, int n_in,
                              void* d_out, int out_size) {
    const float* spatial = (const float*)d_in[0];
    const float* cond    = (const float*)d_in[1];
    const float* lt      = (const float*)d_in[2];
    const float* lp      = (const float*)d_in[3];
    const float* Wq      = (const float*)d_in[4];
    const float* bq      = (const float*)d_in[5];
    const float* Wk      = (const float*)d_in[6];
    const float* bk      = (const float*)d_in[7];
    const float* Wv      = (const float*)d_in[8];
    const float* bv      = (const float*)d_in[9];
    const float* Wo      = (const float*)d_in[10];
    const float* bo      = (const float*)d_in[11];
    const float* Wad     = (const float*)d_in[12];
    const float* bad     = (const float*)d_in[13];
    const float* qn_g    = (const float*)d_in[14];
    const float* qn_b    = (const float*)d_in[15];
    const float* kn_g    = (const float*)d_in[16];
    const float* kn_b    = (const float*)d_in[17];
    const float* nq_g    = (const float*)d_in[18];
    const float* nq_b    = (const float*)d_in[19];
    const float* nkv_g   = (const float*)d_in[20];
    const float* nkv_b   = (const float*)d_in[21];
    float* out = (float*)d_out;

    float *p_k, *p_v, *p_lat;
    __half *p_kvn, *p_ao, *p_wk, *p_wv, *p_wo;
    cudaGetSymbolAddress((void**)&p_kvn, g_kvn);
    cudaGetSymbolAddress((void**)&p_k,   g_k);
    cudaGetSymbolAddress((void**)&p_v,   g_v);
    cudaGetSymbolAddress((void**)&p_ao,  g_ao);
    cudaGetSymbolAddress((void**)&p_lat, g_lat);
    cudaGetSymbolAddress((void**)&p_wk,  g_wk);
    cudaGetSymbolAddress((void**)&p_wv,  g_wv);
    cudaGetSymbolAddress((void**)&p_wo,  g_wo);

    cudaFuncSetAttribute(mma_gemm<0>, cudaFuncAttributeMaxDynamicSharedMemorySize, SMEM_GEMM_BYTES);
    cudaFuncSetAttribute(mma_gemm<1>, cudaFuncAttributeMaxDynamicSharedMemorySize, SMEM_GEMM_BYTES);
    cudaFuncSetAttribute(attn_kernel, cudaFuncAttributeMaxDynamicSharedMemorySize, SMEM_ATTN);

    wcvt_kernel<<<768, 256>>>(Wk, p_wk, Wv, p_wv, Wo, p_wo);
    mod_kernel <<<128, 256>>>(cond, Wad, bad);
    latq_kernel<<<BATCH * JL, 512>>>(lt, lp, Wq, bq, nq_g, nq_b, qn_g, qn_b);
    lnkv_kernel<<<BATCH * NSP, 128>>>(spatial, nkv_g, nkv_b);
    // fused K+V projection (256-row tiles), head-LN on K in epilogue
    mma_gemm<0><<<dim3(8, 64), 256, SMEM_GEMM_BYTES>>>(
        p_kvn, p_wk, p_wv, bk, bv, p_k, p_v, kn_g, kn_b, nullptr);
    attn_kernel<<<dim3(NG, BATCH), 256, SMEM_ATTN>>>();
    // O projection + residual (256-row tiles)
    mma_gemm<1><<<dim3(4, 32), 256, SMEM_GEMM_BYTES>>>(
        p_ao, p_wo, nullptr, bo, nullptr, out, nullptr, nullptr, nullptr, p_lat);
}

// round 6
// speedup vs baseline: 4.5179x; 1.0539x over previous
#include <cuda_runtime.h>
#include <cuda_fp16.h>
#include <math.h>
#include <stdint.h>

#define BATCH 4
#define NSP   4096      // H*W spatial tokens
#define DM    512
#define NH    8
#define DH    64
#define NG    256       // groups (16x16)
#define JL    8         // latents per group
#define NLAT  2048      // NG*JL
#define EPSV  1e-5f

// ---------------- helpers ----------------
#define MMA_F16(d, a, b) \
    asm volatile("mma.sync.aligned.m16n8k16.row.col.f32.f16.f16.f32 " \
        "{%0,%1,%2,%3}, {%4,%5,%6,%7}, {%8,%9}, {%0,%1,%2,%3};" \
        : "+f"((d)[0]), "+f"((d)[1]), "+f"((d)[2]), "+f"((d)[3]) \
        : "r"((a)[0]), "r"((a)[1]), "r"((a)[2]), "r"((a)[3]), \
          "r"((b)[0]), "r"((b)[1]))

#define LDMX4(r0, r1, r2, r3, addr) \
    asm volatile("ldmatrix.sync.aligned.m8n8.x4.shared.b16 {%0,%1,%2,%3}, [%4];" \
        : "=r"(r0), "=r"(r1), "=r"(r2), "=r"(r3) : "r"(addr))

__device__ __forceinline__ void cp_async16(uint32_t smem_addr, const void* gptr) {
    asm volatile("cp.async.cg.shared.global [%0], [%1], 16;"
        :: "r"(smem_addr), "l"(gptr));
}
#define CP_COMMIT()  asm volatile("cp.async.commit_group;" ::: "memory")
#define CP_WAIT(N)   asm volatile("cp.async.wait_group %0;" :: "n"(N) : "memory")

__device__ __forceinline__ uint32_t smem_u32(const void* p) {
    uint32_t a;
    asm("{ .reg .u64 t; cvta.to.shared.u64 t, %1; cvt.u32.u64 %0, t; }" : "=r"(a) : "l"(p));
    return a;
}

// ---------------- scratch (device globals; no allocs allowed) ----------------
__device__ float  g_mod[BATCH * 1024];
__device__ float  g_lat[BATCH * JL * DM];       // modulated latents (residual, fp32)
__device__ float  g_qh [BATCH * JL * DM];       // q heads post head-LN (fp32)
__device__ __half g_kvn[BATCH * NSP * DM];      // LN(spatial), fp16
__device__ __half g_k  [BATCH * NSP * DM];      // k proj, head-LN fused, fp16
__device__ float  g_v  [BATCH * NSP * DM];      // v proj (fp32)
__device__ __half g_ao [BATCH * NLAT * DM];     // attention out, fp16
__device__ __half g_wk [DM * DM];               // fp16 weights
__device__ __half g_wv [DM * DM];
__device__ __half g_wo [DM * DM];

// ---------------- 0) weight fp16 conversion, all 3 weights in one launch ----------------
__global__ void wcvt_kernel(const float* __restrict__ s0, __half* __restrict__ d0,
                            const float* __restrict__ s1, __half* __restrict__ d1,
                            const float* __restrict__ s2, __half* __restrict__ d2) {
    int which = blockIdx.x >> 8;           // 256 blocks per matrix
    int i = (blockIdx.x & 255) * 256 + threadIdx.x;   // float4 index
    const float* src = (which == 0) ? s0 : (which == 1) ? s1 : s2;
    __half*      dst = (which == 0) ? d0 : (which == 1) ? d1 : d2;
    float4 v = ((const float4*)src)[i];
    __half2 h0 = __floats2half2_rn(v.x, v.y);
    __half2 h1 = __floats2half2_rn(v.z, v.w);
    ((__half2*)dst)[2 * i]     = h0;
    ((__half2*)dst)[2 * i + 1] = h1;
}

// ---------------- 1) mod = cond @ Wad^T + bad  (4096 outputs, 8 lanes each) ----------------
__global__ void mod_kernel(const float* __restrict__ cond,
                           const float* __restrict__ Wad,
                           const float* __restrict__ bad) {
    int t = threadIdx.x;
    int o = blockIdx.x * 32 + (t >> 3);    // 0..4095
    int sub = t & 7;
    int b = o >> 10, oo = o & 1023;
    const float4* w  = (const float4*)(Wad + (size_t)oo * 512);
    const float4* cn = (const float4*)(cond + (size_t)b * 512);
    float acc = 0.f;
    #pragma unroll
    for (int k = sub * 16; k < sub * 16 + 16; k++) {
        float4 wv = w[k], cv = cn[k];
        acc += wv.x * cv.x + wv.y * cv.y + wv.z * cv.z + wv.w * cv.w;
    }
    acc += __shfl_xor_sync(0xffffffffu, acc, 1);
    acc += __shfl_xor_sync(0xffffffffu, acc, 2);
    acc += __shfl_xor_sync(0xffffffffu, acc, 4);
    if (sub == 0) g_mod[b * 1024 + oo] = acc + bad[oo];
}

// ------ 2) latents: modulate -> LN -> @Wq^T+bq -> head-LN  (32 rows) ------
__global__ void latq_kernel(const float* __restrict__ lt, const float* __restrict__ lp,
                            const float* __restrict__ Wq, const float* __restrict__ bq,
                            const float* __restrict__ nqg, const float* __restrict__ nqb,
                            const float* __restrict__ qng, const float* __restrict__ qnb) {
    __shared__ float r1[512], r2[512], sval[512];
    int b = blockIdx.x >> 3, j = blockIdx.x & 7;
    int t = threadIdx.x;

    float base  = lt[j * DM + t] + lp[j * DM + t];
    float shift = g_mod[b * 1024 + t];
    float scale = g_mod[b * 1024 + 512 + t];
    float lat   = base * (1.f + scale) + shift;
    g_lat[(size_t)blockIdx.x * DM + t] = lat;

    r1[t] = lat; r2[t] = lat * lat;
    __syncthreads();
    for (int s = 256; s >= 1; s >>= 1) {
        if (t < s) { r1[t] += r1[t + s]; r2[t] += r2[t + s]; }
        __syncthreads();
    }
    float mu  = r1[0] * (1.f / 512.f);
    float var = r2[0] * (1.f / 512.f) - mu * mu;
    float rs  = rsqrtf(var + EPSV);
    sval[t] = (lat - mu) * rs * nqg[t] + nqb[t];
    __syncthreads();

    float acc = bq[t];
    const float4* w  = (const float4*)(Wq + (size_t)t * DM);
    const float4* s4 = (const float4*)sval;
    #pragma unroll 8
    for (int k = 0; k < 128; k++) {
        float4 wv = w[k], sv = s4[k];
        acc += wv.x * sv.x + wv.y * sv.y + wv.z * sv.z + wv.w * sv.w;
    }
    __syncthreads();

    r1[t] = acc; r2[t] = acc * acc;
    __syncthreads();
    for (int s = 32; s >= 1; s >>= 1) {
        if ((t & 63) < s) { r1[t] += r1[t + s]; r2[t] += r2[t + s]; }
        __syncthreads();
    }
    int hb = t & ~63, l = t & 63;
    float mu2  = r1[hb] * (1.f / 64.f);
    float var2 = r2[hb] * (1.f / 64.f) - mu2 * mu2;
    g_qh[(size_t)blockIdx.x * DM + t] =
        (acc - mu2) * rsqrtf(var2 + EPSV) * qng[l] + qnb[l];
}

// ---------------- 3) kv = LN(spatial), fp16 out  (16384 rows) ----------------
__global__ void lnkv_kernel(const float* __restrict__ sp,
                            const float* __restrict__ gg,
                            const float* __restrict__ bb) {
    int row = blockIdx.x, t = threadIdx.x;
    float4 x = ((const float4*)(sp + (size_t)row * DM))[t];
    float s  = x.x + x.y + x.z + x.w;
    float s2 = x.x * x.x + x.y * x.y + x.z * x.z + x.w * x.w;
    #pragma unroll
    for (int o = 16; o >= 1; o >>= 1) {
        s  += __shfl_xor_sync(0xffffffffu, s,  o);
        s2 += __shfl_xor_sync(0xffffffffu, s2, o);
    }
    __shared__ float a1[4], a2[4];
    int w = t >> 5, lane = t & 31;
    if (!lane) { a1[w] = s; a2[w] = s2; }
    __syncthreads();
    s  = a1[0] + a1[1] + a1[2] + a1[3];
    s2 = a2[0] + a2[1] + a2[2] + a2[3];
    float mu  = s * (1.f / 512.f);
    float var = s2 * (1.f / 512.f) - mu * mu;
    float r   = rsqrtf(var + EPSV);
    float4 gv = ((const float4*)gg)[t], bv = ((const float4*)bb)[t];
    __half2 h0 = __floats2half2_rn((x.x - mu) * r * gv.x + bv.x,
                                   (x.y - mu) * r * gv.y + bv.y);
    __half2 h1 = __floats2half2_rn((x.z - mu) * r * gv.z + bv.z,
                                   (x.w - mu) * r * gv.w + bv.w);
    __half2* orow = (__half2*)(g_kvn + (size_t)row * DM);
    orow[2 * t]     = h0;
    orow[2 * t + 1] = h1;
}

// ============ 4) fp16 mma.sync GEMM: 256x128 CTA tile, 64x64 warp tiles, ldmatrix ============
// MODE 0: fused K/V projection (bx 0-3 -> K cols + head-LN -> fp16, 4-7 -> V cols fp32)
// MODE 1: O projection + latent residual (fp32 out)
#define AS_STRIDE 72                              // halfs per row (64 + 8 pad)
#define HALFS_A (256 * AS_STRIDE)                 // 18432
#define HALFS_W (128 * AS_STRIDE)                 // 9216
#define HALFS_STAGE (HALFS_A + HALFS_W)           // 27648
#define SMEM_GEMM_BYTES (2 * HALFS_STAGE * 2)     // 110592

template <int MODE>
__global__ void __launch_bounds__(256, 1) mma_gemm(
    const __half* __restrict__ A,
    const __half* __restrict__ W0, const __half* __restrict__ W1,
    const float* __restrict__ bias0, const float* __restrict__ bias1,
    void* __restrict__ C0v, void* __restrict__ C1v,
    const float* __restrict__ lng, const float* __restrict__ lnb,
    const float* __restrict__ resid) {
    extern __shared__ __half hsm[];

    int tid = threadIdx.x;
    int bx = blockIdx.x, by = blockIdx.y;
    bool isK = (MODE == 0) ? (bx < 4) : false;
    int nb = (MODE == 0) ? (bx & 3) : bx;
    const __half* W   = (MODE == 0 && !isK) ? W1 : W0;
    const float* bias = (MODE == 0 && !isK) ? bias1 : bias0;
    int row0 = by * 256, col0 = nb * 128;
    const __half* Ab = A + (size_t)row0 * 512;
    const __half* Wb = W + (size_t)col0 * 512;

    int warp = tid >> 5, lane = tid & 31;
    int ln4 = lane >> 2, lnm = lane & 3;
    int wm = (warp & 3) * 64, wn = (warp >> 2) * 64;

    uint32_t sbase = smem_u32(hsm);
    int fr = tid >> 3, fc = tid & 7;   // fill: base row (0..31), 16B col (0..7)

    // ldmatrix lane-dependent row/col offsets
    int mat = lane >> 3, lr = lane & 7;
    int aRow = (mat & 1) * 8 + lr;      // + wm + i*16
    int aKof = (mat >> 1) * 8;          // + s*16
    int bRow = (mat >> 1) * 8 + lr;     // + wn + jj*16
    int bKof = (mat & 1) * 8;           // + s*16

    float acc[4][8][4];
    #pragma unroll
    for (int i = 0; i < 4; i++)
        #pragma unroll
        for (int j = 0; j < 8; j++)
            #pragma unroll
            for (int e = 0; e < 4; e++) acc[i][j][e] = 0.f;

    auto fill = [&](int c) {   // chunk c: K cols [c*64, c*64+64)
        int buf = c & 1;
        uint32_t aB = sbase + (uint32_t)buf * HALFS_STAGE * 2;
        uint32_t wB = aB + HALFS_A * 2;
        int kb = c * 64;
        #pragma unroll
        for (int l = 0; l < 8; l++) {
            int r = fr + l * 32;
            cp_async16(aB + (uint32_t)(r * AS_STRIDE + fc * 8) * 2,
                       Ab + (size_t)r * 512 + kb + fc * 8);
        }
        #pragma unroll
        for (int l = 0; l < 4; l++) {
            int r = fr + l * 32;
            cp_async16(wB + (uint32_t)(r * AS_STRIDE + fc * 8) * 2,
                       Wb + (size_t)r * 512 + kb + fc * 8);
        }
    };

    fill(0); CP_COMMIT();

    for (int c = 0; c < 8; c++) {
        if (c + 1 < 8) { fill(c + 1); CP_COMMIT(); CP_WAIT(1); }
        else           { CP_WAIT(0); }
        __syncthreads();

        uint32_t aBufAddr = sbase + (uint32_t)(c & 1) * HALFS_STAGE * 2;
        uint32_t wBufAddr = aBufAddr + HALFS_A * 2;

        #pragma unroll
        for (int s = 0; s < 4; s++) {   // k16 steps within chunk
            uint32_t a[4][4], bfr[8][2];
            #pragma unroll
            for (int i = 0; i < 4; i++) {
                uint32_t addr = aBufAddr +
                    (uint32_t)((wm + i * 16 + aRow) * AS_STRIDE + s * 16 + aKof) * 2;
                LDMX4(a[i][0], a[i][1], a[i][2], a[i][3], addr);
            }
            #pragma unroll
            for (int jj = 0; jj < 4; jj++) {
                uint32_t addr = wBufAddr +
                    (uint32_t)((wn + jj * 16 + bRow) * AS_STRIDE + s * 16 + bKof) * 2;
                LDMX4(bfr[2 * jj][0], bfr[2 * jj][1],
                      bfr[2 * jj + 1][0], bfr[2 * jj + 1][1], addr);
            }
            #pragma unroll
            for (int i = 0; i < 4; i++)
                #pragma unroll
                for (int j = 0; j < 8; j++)
                    MMA_F16(acc[i][j], a[i], bfr[j]);
        }
        __syncthreads();
    }

    // ---- register-resident epilogue: bias (+head-LN | +residual), direct stores ----
    float2 b2[8];
    #pragma unroll
    for (int j = 0; j < 8; j++)
        b2[j] = *(const float2*)(bias + col0 + wn + j * 8 + 2 * lnm);
    float2 g2[8], be2[8];
    if (MODE == 0 && isK) {
        #pragma unroll
        for (int j = 0; j < 8; j++) {
            g2[j]  = *(const float2*)(lng + j * 8 + 2 * lnm);
            be2[j] = *(const float2*)(lnb + j * 8 + 2 * lnm);
        }
    }

    #pragma unroll
    for (int i = 0; i < 4; i++) {
        #pragma unroll
        for (int h = 0; h < 2; h++) {
            int row = row0 + wm + i * 16 + ln4 + 8 * h;
            float vx[8], vy[8];
            #pragma unroll
            for (int j = 0; j < 8; j++) {
                vx[j] = acc[i][j][2 * h]     + b2[j].x;
                vy[j] = acc[i][j][2 * h + 1] + b2[j].y;
            }
            if (MODE == 0 && isK) {
                float s = 0.f, s2 = 0.f;
                #pragma unroll
                for (int j = 0; j < 8; j++) {
                    s  += vx[j] + vy[j];
                    s2 += vx[j] * vx[j] + vy[j] * vy[j];
                }
                s  += __shfl_xor_sync(0xffffffffu, s, 1);
                s  += __shfl_xor_sync(0xffffffffu, s, 2);
                s2 += __shfl_xor_sync(0xffffffffu, s2, 1);
                s2 += __shfl_xor_sync(0xffffffffu, s2, 2);
                float mu  = s * (1.f / 64.f);
                float var = s2 * (1.f / 64.f) - mu * mu;
                float rq  = rsqrtf(var + EPSV);
                // K output: head-LN then fp16
                __half* cr = (__half*)C0v + (size_t)row * 512 + col0 + wn;
                #pragma unroll
                for (int j = 0; j < 8; j++) {
                    float ox = (vx[j] - mu) * rq * g2[j].x + be2[j].x;
                    float oy = (vy[j] - mu) * rq * g2[j].y + be2[j].y;
                    *(__half2*)(cr + j * 8 + 2 * lnm) = __floats2half2_rn(ox, oy);
                }
            } else if (MODE == 0) {
                float* cr = (float*)C1v + (size_t)row * 512 + col0 + wn;
                #pragma unroll
                for (int j = 0; j < 8; j++)
                    *(float2*)(cr + j * 8 + 2 * lnm) = make_float2(vx[j], vy[j]);
            } else {
                const float* rres = resid
                    + (size_t)(((row >> 11) << 3) + (row & 7)) * 512 + col0 + wn;
                #pragma unroll
                for (int j = 0; j < 8; j++) {
                    float2 rv = *(const float2*)(rres + j * 8 + 2 * lnm);
                    vx[j] += rv.x; vy[j] += rv.y;
                }
                float* cr = (float*)C0v + (size_t)row * 512 + col0 + wn;
                #pragma unroll
                for (int j = 0; j < 8; j++)
                    *(float2*)(cr + j * 8 + 2 * lnm) = make_float2(vx[j], vy[j]);
            }
        }
    }
}

// ---------------- 6) grouped attention: per (b,g), 8 heads x 8 q x 16 k ----------------
#define KS_STRIDE 514
#define SMEM_ATTN ((4096 + 16 * KS_STRIDE + 1024) * 4)

__global__ void __launch_bounds__(256) attn_kernel() {
    extern __shared__ float sm[];
    float* qs = sm;
    float* ks = sm + 4096;
    float* ps = sm + 4096 + 16 * KS_STRIDE;
    __shared__ int tok[16];

    int g = blockIdx.x, b = blockIdx.y;
    int tid = threadIdx.x;
    if (tid < 16) {
        int gr = g >> 4, gc = g & 15;
        tok[tid] = ((gr << 2) + (tid >> 2)) * 64 + (gc << 2) + (tid & 3);
    }
    __syncthreads();

    {
        const float4* src = (const float4*)(g_qh + (size_t)b * JL * DM);
        float4* dst = (float4*)qs;
        #pragma unroll
        for (int p = tid; p < 1024; p += 256) dst[p] = src[p];
    }
    // K rows: fp16 -> fp32 smem
    for (int p = tid; p < 16 * 256; p += 256) {
        int r = p >> 8, c2 = p & 255;
        __half2 hv = ((const __half2*)(g_k + ((size_t)(b * NSP + tok[r])) * DM))[c2];
        float2 f = __half22float2(hv);
        ks[r * KS_STRIDE + 2 * c2]     = f.x;
        ks[r * KS_STRIDE + 2 * c2 + 1] = f.y;
    }
    __syncthreads();

    int h = tid >> 5, lane = tid & 31;

    float pr[4];
    #pragma unroll
    for (int i = 0; i < 4; i++) {
        int p = lane + 32 * i;
        int q = p >> 4, k = p & 15;
        const float* qrow = qs + q * DM + h * DH;
        const float* krow = ks + k * KS_STRIDE + h * DH;
        float s = 0.f;
        #pragma unroll
        for (int d = 0; d < DH; d++) s += qrow[d] * krow[d];
        pr[i] = s * 0.125f;
    }
    #pragma unroll
    for (int i = 0; i < 4; i++) {
        float m = pr[i];
        #pragma unroll
        for (int o = 1; o < 16; o <<= 1) m = fmaxf(m, __shfl_xor_sync(0xffffffffu, m, o));
        float e = __expf(pr[i] - m);
        float ssum = e;
        #pragma unroll
        for (int o = 1; o < 16; o <<= 1) ssum += __shfl_xor_sync(0xffffffffu, ssum, o);
        pr[i] = e / ssum;
    }
    #pragma unroll
    for (int i = 0; i < 4; i++) ps[h * 128 + lane + 32 * i] = pr[i];
    __syncwarp();

    float v0[16], v1[16];
    #pragma unroll
    for (int k = 0; k < 16; k++) {
        const float* vrow = g_v + ((size_t)(b * NSP + tok[k])) * DM + h * DH;
        v0[k] = vrow[lane]; v1[k] = vrow[lane + 32];
    }
    #pragma unroll
    for (int q = 0; q < 8; q++) {
        float o0 = 0.f, o1 = 0.f;
        #pragma unroll
        for (int k = 0; k < 16; k++) {
            float pqk = ps[h * 128 + q * 16 + k];
            o0 += pqk * v0[k]; o1 += pqk * v1[k];
        }
        size_t base = ((size_t)(b * NLAT + g * JL + q)) * DM + h * DH;
        g_ao[base + lane]      = __float2half_rn(o0);
        g_ao[base + lane + 32] = __float2half_rn(o1);
    }
}

// ---------------- launch ----------------
extern "C" void kernel_launch(void* const* d_in, const int* in_sizes, int n_in,
                              void* d_out, int out_size) {
    const float* spatial = (const float*)d_in[0];
    const float* cond    = (const float*)d_in[1];
    const float* lt      = (const float*)d_in[2];
    const float* lp      = (const float*)d_in[3];
    const float* Wq      = (const float*)d_in[4];
    const float* bq      = (const float*)d_in[5];
    const float* Wk      = (const float*)d_in[6];
    const float* bk      = (const float*)d_in[7];
    const float* Wv      = (const float*)d_in[8];
    const float* bv      = (const float*)d_in[9];
    const float* Wo      = (const float*)d_in[10];
    const float* bo      = (const float*)d_in[11];
    const float* Wad     = (const float*)d_in[12];
    const float* bad     = (const float*)d_in[13];
    const float* qn_g    = (const float*)d_in[14];
    const float* qn_b    = (const float*)d_in[15];
    const float* kn_g    = (const float*)d_in[16];
    const float* kn_b    = (const float*)d_in[17];
    const float* nq_g    = (const float*)d_in[18];
    const float* nq_b    = (const float*)d_in[19];
    const float* nkv_g   = (const float*)d_in[20];
    const float* nkv_b   = (const float*)d_in[21];
    float* out = (float*)d_out;

    float *p_v, *p_lat;
    __half *p_kvn, *p_k, *p_ao, *p_wk, *p_wv, *p_wo;
    cudaGetSymbolAddress((void**)&p_kvn, g_kvn);
    cudaGetSymbolAddress((void**)&p_k,   g_k);
    cudaGetSymbolAddress((void**)&p_v,   g_v);
    cudaGetSymbolAddress((void**)&p_ao,  g_ao);
    cudaGetSymbolAddress((void**)&p_lat, g_lat);
    cudaGetSymbolAddress((void**)&p_wk,  g_wk);
    cudaGetSymbolAddress((void**)&p_wv,  g_wv);
    cudaGetSymbolAddress((void**)&p_wo,  g_wo);

    cudaFuncSetAttribute(mma_gemm<0>, cudaFuncAttributeMaxDynamicSharedMemorySize, SMEM_GEMM_BYTES);
    cudaFuncSetAttribute(mma_gemm<1>, cudaFuncAttributeMaxDynamicSharedMemorySize, SMEM_GEMM_BYTES);
    cudaFuncSetAttribute(attn_kernel, cudaFuncAttributeMaxDynamicSharedMemorySize, SMEM_ATTN);

    wcvt_kernel<<<768, 256>>>(Wk, p_wk, Wv, p_wv, Wo, p_wo);
    mod_kernel <<<128, 256>>>(cond, Wad, bad);
    latq_kernel<<<BATCH * JL, 512>>>(lt, lp, Wq, bq, nq_g, nq_b, qn_g, qn_b);
    lnkv_kernel<<<BATCH * NSP, 128>>>(spatial, nkv_g, nkv_b);
    // fused K+V projection (256-row tiles), head-LN on K in epilogue -> fp16 K
    mma_gemm<0><<<dim3(8, 64), 256, SMEM_GEMM_BYTES>>>(
        p_kvn, p_wk, p_wv, bk, bv, (void*)p_k, (void*)p_v, kn_g, kn_b, nullptr);
    attn_kernel<<<dim3(NG, BATCH), 256, SMEM_ATTN>>>();
    // O projection + residual (256-row tiles), fp32 out
    mma_gemm<1><<<dim3(4, 32), 256, SMEM_GEMM_BYTES>>>(
        p_ao, p_wo, nullptr, bo, nullptr, (void*)out, nullptr, nullptr, nullptr, p_lat);
}

// round 7
// speedup vs baseline: 4.8809x; 1.0803x over previous
#include <cuda_runtime.h>
#include <cuda_fp16.h>
#include <math.h>
#include <stdint.h>

#define BATCH 4
#define NSP   4096      // H*W spatial tokens
#define DM    512
#define NH    8
#define DH    64
#define NG    256       // groups (16x16)
#define JL    8         // latents per group
#define NLAT  2048      // NG*JL
#define EPSV  1e-5f

// ---------------- helpers ----------------
#define MMA_F16(d, a, b) \
    asm volatile("mma.sync.aligned.m16n8k16.row.col.f32.f16.f16.f32 " \
        "{%0,%1,%2,%3}, {%4,%5,%6,%7}, {%8,%9}, {%0,%1,%2,%3};" \
        : "+f"((d)[0]), "+f"((d)[1]), "+f"((d)[2]), "+f"((d)[3]) \
        : "r"((a)[0]), "r"((a)[1]), "r"((a)[2]), "r"((a)[3]), \
          "r"((b)[0]), "r"((b)[1]))

#define LDMX4(r0, r1, r2, r3, addr) \
    asm volatile("ldmatrix.sync.aligned.m8n8.x4.shared.b16 {%0,%1,%2,%3}, [%4];" \
        : "=r"(r0), "=r"(r1), "=r"(r2), "=r"(r3) : "r"(addr))

__device__ __forceinline__ void cp_async16(uint32_t smem_addr, const void* gptr) {
    asm volatile("cp.async.cg.shared.global [%0], [%1], 16;"
        :: "r"(smem_addr), "l"(gptr));
}
#define CP_COMMIT()  asm volatile("cp.async.commit_group;" ::: "memory")
#define CP_WAIT(N)   asm volatile("cp.async.wait_group %0;" :: "n"(N) : "memory")

__device__ __forceinline__ uint32_t smem_u32(const void* p) {
    uint32_t a;
    asm("{ .reg .u64 t; cvta.to.shared.u64 t, %1; cvt.u32.u64 %0, t; }" : "=r"(a) : "l"(p));
    return a;
}

// ---------------- scratch (device globals; no allocs allowed) ----------------
__device__ float  g_mod[BATCH * 1024];
__device__ float  g_lat[BATCH * JL * DM];       // modulated latents (residual, fp32)
__device__ float  g_qh [BATCH * JL * DM];       // q heads post head-LN (fp32)
__device__ __half g_kvn[BATCH * NSP * DM];      // LN(spatial), fp16
__device__ __half g_k  [BATCH * NSP * DM];      // k proj, head-LN fused, fp16
__device__ __half g_v  [BATCH * NSP * DM];      // v proj, fp16
__device__ __half g_ao [BATCH * NLAT * DM];     // attention out, fp16
__device__ __half g_wk [DM * DM];               // fp16 weights
__device__ __half g_wv [DM * DM];
__device__ __half g_wo [DM * DM];

// ---------------- 0) weight fp16 conversion, all 3 weights in one launch ----------------
__global__ void wcvt_kernel(const float* __restrict__ s0, __half* __restrict__ d0,
                            const float* __restrict__ s1, __half* __restrict__ d1,
                            const float* __restrict__ s2, __half* __restrict__ d2) {
    int which = blockIdx.x >> 8;           // 256 blocks per matrix
    int i = (blockIdx.x & 255) * 256 + threadIdx.x;   // float4 index
    const float* src = (which == 0) ? s0 : (which == 1) ? s1 : s2;
    __half*      dst = (which == 0) ? d0 : (which == 1) ? d1 : d2;
    float4 v = ((const float4*)src)[i];
    __half2 h0 = __floats2half2_rn(v.x, v.y);
    __half2 h1 = __floats2half2_rn(v.z, v.w);
    ((__half2*)dst)[2 * i]     = h0;
    ((__half2*)dst)[2 * i + 1] = h1;
}

// ---------------- 1) mod = cond @ Wad^T + bad  (4096 outputs, 8 lanes each) ----------------
__global__ void mod_kernel(const float* __restrict__ cond,
                           const float* __restrict__ Wad,
                           const float* __restrict__ bad) {
    int t = threadIdx.x;
    int o = blockIdx.x * 32 + (t >> 3);    // 0..4095
    int sub = t & 7;
    int b = o >> 10, oo = o & 1023;
    const float4* w  = (const float4*)(Wad + (size_t)oo * 512);
    const float4* cn = (const float4*)(cond + (size_t)b * 512);
    float acc = 0.f;
    #pragma unroll
    for (int k = sub * 16; k < sub * 16 + 16; k++) {
        float4 wv = w[k], cv = cn[k];
        acc += wv.x * cv.x + wv.y * cv.y + wv.z * cv.z + wv.w * cv.w;
    }
    acc += __shfl_xor_sync(0xffffffffu, acc, 1);
    acc += __shfl_xor_sync(0xffffffffu, acc, 2);
    acc += __shfl_xor_sync(0xffffffffu, acc, 4);
    if (sub == 0) g_mod[b * 1024 + oo] = acc + bad[oo];
}

// ------ 2) latents: modulate -> LN -> @Wq^T+bq -> head-LN  (32 rows) ------
__global__ void latq_kernel(const float* __restrict__ lt, const float* __restrict__ lp,
                            const float* __restrict__ Wq, const float* __restrict__ bq,
                            const float* __restrict__ nqg, const float* __restrict__ nqb,
                            const float* __restrict__ qng, const float* __restrict__ qnb) {
    __shared__ float r1[512], r2[512], sval[512];
    int b = blockIdx.x >> 3, j = blockIdx.x & 7;
    int t = threadIdx.x;

    float base  = lt[j * DM + t] + lp[j * DM + t];
    float shift = g_mod[b * 1024 + t];
    float scale = g_mod[b * 1024 + 512 + t];
    float lat   = base * (1.f + scale) + shift;
    g_lat[(size_t)blockIdx.x * DM + t] = lat;

    r1[t] = lat; r2[t] = lat * lat;
    __syncthreads();
    for (int s = 256; s >= 1; s >>= 1) {
        if (t < s) { r1[t] += r1[t + s]; r2[t] += r2[t + s]; }
        __syncthreads();
    }
    float mu  = r1[0] * (1.f / 512.f);
    float var = r2[0] * (1.f / 512.f) - mu * mu;
    float rs  = rsqrtf(var + EPSV);
    sval[t] = (lat - mu) * rs * nqg[t] + nqb[t];
    __syncthreads();

    float acc = bq[t];
    const float4* w  = (const float4*)(Wq + (size_t)t * DM);
    const float4* s4 = (const float4*)sval;
    #pragma unroll 8
    for (int k = 0; k < 128; k++) {
        float4 wv = w[k], sv = s4[k];
        acc += wv.x * sv.x + wv.y * sv.y + wv.z * sv.z + wv.w * sv.w;
    }
    __syncthreads();

    r1[t] = acc; r2[t] = acc * acc;
    __syncthreads();
    for (int s = 32; s >= 1; s >>= 1) {
        if ((t & 63) < s) { r1[t] += r1[t + s]; r2[t] += r2[t + s]; }
        __syncthreads();
    }
    int hb = t & ~63, l = t & 63;
    float mu2  = r1[hb] * (1.f / 64.f);
    float var2 = r2[hb] * (1.f / 64.f) - mu2 * mu2;
    g_qh[(size_t)blockIdx.x * DM + t] =
        (acc - mu2) * rsqrtf(var2 + EPSV) * qng[l] + qnb[l];
}

// ---------------- 3) kv = LN(spatial), fp16 out  (16384 rows) ----------------
__global__ void lnkv_kernel(const float* __restrict__ sp,
                            const float* __restrict__ gg,
                            const float* __restrict__ bb) {
    int row = blockIdx.x, t = threadIdx.x;
    float4 x = ((const float4*)(sp + (size_t)row * DM))[t];
    float s  = x.x + x.y + x.z + x.w;
    float s2 = x.x * x.x + x.y * x.y + x.z * x.z + x.w * x.w;
    #pragma unroll
    for (int o = 16; o >= 1; o >>= 1) {
        s  += __shfl_xor_sync(0xffffffffu, s,  o);
        s2 += __shfl_xor_sync(0xffffffffu, s2, o);
    }
    __shared__ float a1[4], a2[4];
    int w = t >> 5, lane = t & 31;
    if (!lane) { a1[w] = s; a2[w] = s2; }
    __syncthreads();
    s  = a1[0] + a1[1] + a1[2] + a1[3];
    s2 = a2[0] + a2[1] + a2[2] + a2[3];
    float mu  = s * (1.f / 512.f);
    float var = s2 * (1.f / 512.f) - mu * mu;
    float r   = rsqrtf(var + EPSV);
    float4 gv = ((const float4*)gg)[t], bv = ((const float4*)bb)[t];
    __half2 h0 = __floats2half2_rn((x.x - mu) * r * gv.x + bv.x,
                                   (x.y - mu) * r * gv.y + bv.y);
    __half2 h1 = __floats2half2_rn((x.z - mu) * r * gv.z + bv.z,
                                   (x.w - mu) * r * gv.w + bv.w);
    __half2* orow = (__half2*)(g_kvn + (size_t)row * DM);
    orow[2 * t]     = h0;
    orow[2 * t + 1] = h1;
}

// ===== 4) fp16 mma.sync GEMM: 128x128 CTA tile, 4 warps (64x64), 3-stage pipeline =====
// MODE 0: fused K/V projection (bx 0-3 -> K cols + head-LN -> fp16, 4-7 -> V cols fp16)
// MODE 1: O projection + latent residual (fp32 out)
#define AS_STRIDE 72                              // halfs per row (64 + 8 pad)
#define HALFS_A (128 * AS_STRIDE)                 // 9216
#define HALFS_STAGE (2 * HALFS_A)                 // 18432 (A tile + W tile)
#define STAGE_BYTES (HALFS_STAGE * 2)             // 36864
#define SMEM_GEMM_BYTES (3 * STAGE_BYTES)         // 110592

template <int MODE>
__global__ void __launch_bounds__(128, 2) mma_gemm(
    const __half* __restrict__ A,
    const __half* __restrict__ W0, const __half* __restrict__ W1,
    const float* __restrict__ bias0, const float* __restrict__ bias1,
    void* __restrict__ C0v, void* __restrict__ C1v,
    const float* __restrict__ lng, const float* __restrict__ lnb,
    const float* __restrict__ resid) {
    extern __shared__ __half hsm[];

    int tid = threadIdx.x;
    int bx = blockIdx.x, by = blockIdx.y;
    bool isK = (MODE == 0) ? (bx < 4) : false;
    int nb = (MODE == 0) ? (bx & 3) : bx;
    const __half* W   = (MODE == 0 && !isK) ? W1 : W0;
    const float* bias = (MODE == 0 && !isK) ? bias1 : bias0;
    int row0 = by * 128, col0 = nb * 128;
    const __half* Ab = A + (size_t)row0 * 512;
    const __half* Wb = W + (size_t)col0 * 512;

    int warp = tid >> 5, lane = tid & 31;
    int ln4 = lane >> 2, lnm = lane & 3;
    int wm = (warp & 1) * 64, wn = (warp >> 1) * 64;

    uint32_t sbase = smem_u32(hsm);
    int fr = tid >> 3, fc = tid & 7;   // fill: base row (0..15), 16B col (0..7)

    // ldmatrix lane-dependent row/col offsets
    int mat = lane >> 3, lr = lane & 7;
    int aRow = (mat & 1) * 8 + lr;      // + wm + i*16
    int aKof = (mat >> 1) * 8;          // + s*16
    int bRow = (mat >> 1) * 8 + lr;     // + wn + jj*16
    int bKof = (mat & 1) * 8;           // + s*16

    float acc[4][8][4];
    #pragma unroll
    for (int i = 0; i < 4; i++)
        #pragma unroll
        for (int j = 0; j < 8; j++)
            #pragma unroll
            for (int e = 0; e < 4; e++) acc[i][j][e] = 0.f;

    auto fill = [&](int c, int st) {   // chunk c into stage st
        uint32_t aB = sbase + (uint32_t)st * STAGE_BYTES;
        uint32_t wB = aB + HALFS_A * 2;
        int kb = c * 64;
        #pragma unroll
        for (int l = 0; l < 8; l++) {
            int r = fr + l * 16;
            cp_async16(aB + (uint32_t)(r * AS_STRIDE + fc * 8) * 2,
                       Ab + (size_t)r * 512 + kb + fc * 8);
            cp_async16(wB + (uint32_t)(r * AS_STRIDE + fc * 8) * 2,
                       Wb + (size_t)r * 512 + kb + fc * 8);
        }
    };

    fill(0, 0); CP_COMMIT();
    fill(1, 1); CP_COMMIT();

    int st = 0, stNext = 2;   // stage of chunk c; stage to fill next
    for (int c = 0; c < 8; c++) {
        if (c + 2 < 8) {
            fill(c + 2, stNext); CP_COMMIT();
            if (++stNext == 3) stNext = 0;
            CP_WAIT(2);
        } else if (c == 6) {
            CP_WAIT(1);
        } else {
            CP_WAIT(0);
        }
        __syncthreads();

        uint32_t aBufAddr = sbase + (uint32_t)st * STAGE_BYTES;
        uint32_t wBufAddr = aBufAddr + HALFS_A * 2;

        #pragma unroll
        for (int s = 0; s < 4; s++) {   // k16 steps within chunk
            uint32_t a[4][4], bfr[8][2];
            #pragma unroll
            for (int i = 0; i < 4; i++) {
                uint32_t addr = aBufAddr +
                    (uint32_t)((wm + i * 16 + aRow) * AS_STRIDE + s * 16 + aKof) * 2;
                LDMX4(a[i][0], a[i][1], a[i][2], a[i][3], addr);
            }
            #pragma unroll
            for (int jj = 0; jj < 4; jj++) {
                uint32_t addr = wBufAddr +
                    (uint32_t)((wn + jj * 16 + bRow) * AS_STRIDE + s * 16 + bKof) * 2;
                LDMX4(bfr[2 * jj][0], bfr[2 * jj][1],
                      bfr[2 * jj + 1][0], bfr[2 * jj + 1][1], addr);
            }
            #pragma unroll
            for (int i = 0; i < 4; i++)
                #pragma unroll
                for (int j = 0; j < 8; j++)
                    MMA_F16(acc[i][j], a[i], bfr[j]);
        }
        __syncthreads();
        if (++st == 3) st = 0;
    }

    // ---- register-resident epilogue: bias (+head-LN | +residual), direct stores ----
    float2 b2[8];
    #pragma unroll
    for (int j = 0; j < 8; j++)
        b2[j] = *(const float2*)(bias + col0 + wn + j * 8 + 2 * lnm);
    float2 g2[8], be2[8];
    if (MODE == 0 && isK) {
        #pragma unroll
        for (int j = 0; j < 8; j++) {
            g2[j]  = *(const float2*)(lng + j * 8 + 2 * lnm);
            be2[j] = *(const float2*)(lnb + j * 8 + 2 * lnm);
        }
    }

    #pragma unroll
    for (int i = 0; i < 4; i++) {
        #pragma unroll
        for (int h = 0; h < 2; h++) {
            int row = row0 + wm + i * 16 + ln4 + 8 * h;
            float vx[8], vy[8];
            #pragma unroll
            for (int j = 0; j < 8; j++) {
                vx[j] = acc[i][j][2 * h]     + b2[j].x;
                vy[j] = acc[i][j][2 * h + 1] + b2[j].y;
            }
            if (MODE == 0) {
                if (isK) {
                    float s = 0.f, s2 = 0.f;
                    #pragma unroll
                    for (int j = 0; j < 8; j++) {
                        s  += vx[j] + vy[j];
                        s2 += vx[j] * vx[j] + vy[j] * vy[j];
                    }
                    s  += __shfl_xor_sync(0xffffffffu, s, 1);
                    s  += __shfl_xor_sync(0xffffffffu, s, 2);
                    s2 += __shfl_xor_sync(0xffffffffu, s2, 1);
                    s2 += __shfl_xor_sync(0xffffffffu, s2, 2);
                    float mu  = s * (1.f / 64.f);
                    float var = s2 * (1.f / 64.f) - mu * mu;
                    float rq  = rsqrtf(var + EPSV);
                    __half* cr = (__half*)C0v + (size_t)row * 512 + col0 + wn;
                    #pragma unroll
                    for (int j = 0; j < 8; j++) {
                        float ox = (vx[j] - mu) * rq * g2[j].x + be2[j].x;
                        float oy = (vy[j] - mu) * rq * g2[j].y + be2[j].y;
                        *(__half2*)(cr + j * 8 + 2 * lnm) = __floats2half2_rn(ox, oy);
                    }
                } else {
                    __half* cr = (__half*)C1v + (size_t)row * 512 + col0 + wn;
                    #pragma unroll
                    for (int j = 0; j < 8; j++)
                        *(__half2*)(cr + j * 8 + 2 * lnm) = __floats2half2_rn(vx[j], vy[j]);
                }
            } else {
                const float* rres = resid
                    + (size_t)(((row >> 11) << 3) + (row & 7)) * 512 + col0 + wn;
                #pragma unroll
                for (int j = 0; j < 8; j++) {
                    float2 rv = *(const float2*)(rres + j * 8 + 2 * lnm);
                    vx[j] += rv.x; vy[j] += rv.y;
                }
                float* cr = (float*)C0v + (size_t)row * 512 + col0 + wn;
                #pragma unroll
                for (int j = 0; j < 8; j++)
                    *(float2*)(cr + j * 8 + 2 * lnm) = make_float2(vx[j], vy[j]);
            }
        }
    }
}

// ---------------- 6) grouped attention: per (b,g), 8 heads x 8 q x 16 k ----------------
#define KS_STRIDE 514
#define SMEM_ATTN ((4096 + 16 * KS_STRIDE + 1024) * 4)

__global__ void __launch_bounds__(256) attn_kernel() {
    extern __shared__ float sm[];
    float* qs = sm;
    float* ks = sm + 4096;
    float* ps = sm + 4096 + 16 * KS_STRIDE;
    __shared__ int tok[16];

    int g = blockIdx.x, b = blockIdx.y;
    int tid = threadIdx.x;
    if (tid < 16) {
        int gr = g >> 4, gc = g & 15;
        tok[tid] = ((gr << 2) + (tid >> 2)) * 64 + (gc << 2) + (tid & 3);
    }
    __syncthreads();

    {
        const float4* src = (const float4*)(g_qh + (size_t)b * JL * DM);
        float4* dst = (float4*)qs;
        #pragma unroll
        for (int p = tid; p < 1024; p += 256) dst[p] = src[p];
    }
    // K rows: fp16 -> fp32 smem
    for (int p = tid; p < 16 * 256; p += 256) {
        int r = p >> 8, c2 = p & 255;
        __half2 hv = ((const __half2*)(g_k + ((size_t)(b * NSP + tok[r])) * DM))[c2];
        float2 f = __half22float2(hv);
        ks[r * KS_STRIDE + 2 * c2]     = f.x;
        ks[r * KS_STRIDE + 2 * c2 + 1] = f.y;
    }
    __syncthreads();

    int h = tid >> 5, lane = tid & 31;

    float pr[4];
    #pragma unroll
    for (int i = 0; i < 4; i++) {
        int p = lane + 32 * i;
        int q = p >> 4, k = p & 15;
        const float* qrow = qs + q * DM + h * DH;
        const float* krow = ks + k * KS_STRIDE + h * DH;
        float s = 0.f;
        #pragma unroll
        for (int d = 0; d < DH; d++) s += qrow[d] * krow[d];
        pr[i] = s * 0.125f;
    }
    #pragma unroll
    for (int i = 0; i < 4; i++) {
        float m = pr[i];
        #pragma unroll
        for (int o = 1; o < 16; o <<= 1) m = fmaxf(m, __shfl_xor_sync(0xffffffffu, m, o));
        float e = __expf(pr[i] - m);
        float ssum = e;
        #pragma unroll
        for (int o = 1; o < 16; o <<= 1) ssum += __shfl_xor_sync(0xffffffffu, ssum, o);
        pr[i] = e / ssum;
    }
    #pragma unroll
    for (int i = 0; i < 4; i++) ps[h * 128 + lane + 32 * i] = pr[i];
    __syncwarp();

    float v0[16], v1[16];
    #pragma unroll
    for (int k = 0; k < 16; k++) {
        const __half* vrow = g_v + ((size_t)(b * NSP + tok[k])) * DM + h * DH;
        v0[k] = __half2float(vrow[lane]);
        v1[k] = __half2float(vrow[lane + 32]);
    }
    #pragma unroll
    for (int q = 0; q < 8; q++) {
        float o0 = 0.f, o1 = 0.f;
        #pragma unroll
        for (int k = 0; k < 16; k++) {
            float pqk = ps[h * 128 + q * 16 + k];
            o0 += pqk * v0[k]; o1 += pqk * v1[k];
        }
        size_t base = ((size_t)(b * NLAT + g * JL + q)) * DM + h * DH;
        g_ao[base + lane]      = __float2half_rn(o0);
        g_ao[base + lane + 32] = __float2half_rn(o1);
    }
}

// ---------------- launch ----------------
extern "C" void kernel_launch(void* const* d_in, const int* in_sizes, int n_in,
                              void* d_out, int out_size) {
    const float* spatial = (const float*)d_in[0];
    const float* cond    = (const float*)d_in[1];
    const float* lt      = (const float*)d_in[2];
    const float* lp      = (const float*)d_in[3];
    const float* Wq      = (const float*)d_in[4];
    const float* bq      = (const float*)d_in[5];
    const float* Wk      = (const float*)d_in[6];
    const float* bk      = (const float*)d_in[7];
    const float* Wv      = (const float*)d_in[8];
    const float* bv      = (const float*)d_in[9];
    const float* Wo      = (const float*)d_in[10];
    const float* bo      = (const float*)d_in[11];
    const float* Wad     = (const float*)d_in[12];
    const float* bad     = (const float*)d_in[13];
    const float* qn_g    = (const float*)d_in[14];
    const float* qn_b    = (const float*)d_in[15];
    const float* kn_g    = (const float*)d_in[16];
    const float* kn_b    = (const float*)d_in[17];
    const float* nq_g    = (const float*)d_in[18];
    const float* nq_b    = (const float*)d_in[19];
    const float* nkv_g   = (const float*)d_in[20];
    const float* nkv_b   = (const float*)d_in[21];
    float* out = (float*)d_out;

    float *p_lat;
    __half *p_kvn, *p_k, *p_v, *p_ao, *p_wk, *p_wv, *p_wo;
    cudaGetSymbolAddress((void**)&p_kvn, g_kvn);
    cudaGetSymbolAddress((void**)&p_k,   g_k);
    cudaGetSymbolAddress((void**)&p_v,   g_v);
    cudaGetSymbolAddress((void**)&p_ao,  g_ao);
    cudaGetSymbolAddress((void**)&p_lat, g_lat);
    cudaGetSymbolAddress((void**)&p_wk,  g_wk);
    cudaGetSymbolAddress((void**)&p_wv,  g_wv);
    cudaGetSymbolAddress((void**)&p_wo,  g_wo);

    cudaFuncSetAttribute(mma_gemm<0>, cudaFuncAttributeMaxDynamicSharedMemorySize, SMEM_GEMM_BYTES);
    cudaFuncSetAttribute(mma_gemm<1>, cudaFuncAttributeMaxDynamicSharedMemorySize, SMEM_GEMM_BYTES);
    cudaFuncSetAttribute(attn_kernel, cudaFuncAttributeMaxDynamicSharedMemorySize, SMEM_ATTN);

    wcvt_kernel<<<768, 256>>>(Wk, p_wk, Wv, p_wv, Wo, p_wo);
    mod_kernel <<<128, 256>>>(cond, Wad, bad);
    latq_kernel<<<BATCH * JL, 512>>>(lt, lp, Wq, bq, nq_g, nq_b, qn_g, qn_b);
    lnkv_kernel<<<BATCH * NSP, 128>>>(spatial, nkv_g, nkv_b);
    // fused K+V projection (128x128 tiles), head-LN on K in epilogue -> fp16 K, fp16 V
    mma_gemm<0><<<dim3(8, 128), 128, SMEM_GEMM_BYTES>>>(
        p_kvn, p_wk, p_wv, bk, bv, (void*)p_k, (void*)p_v, kn_g, kn_b, nullptr);
    attn_kernel<<<dim3(NG, BATCH), 256, SMEM_ATTN>>>();
    // O projection + residual (128x128 tiles), fp32 out
    mma_gemm<1><<<dim3(4, 64), 128, SMEM_GEMM_BYTES>>>(
        p_ao, p_wo, nullptr, bo, nullptr, (void*)out, nullptr, nullptr, nullptr, p_lat);
}